// round 3
// baseline (speedup 1.0000x reference)
#include <cuda_runtime.h>
#include <cstddef>

#define N_NODES  50000
#define N_EDGES  800000
#define N_GRAPHS 1024
#define H        128
#define NLAYERS  5
#define EPS      1e-5f

// ---------------- device scratch (static globals; no allocation) ----------------
__device__ float g_x[N_NODES * H];                 // node features (25.6 MB)
__device__ float g_e[(size_t)N_EDGES * H];         // edge features (409.6 MB)
__device__ float g_aggr[N_NODES * H];              // per-layer aggregation (25.6 MB)
__device__ float g_cnt[N_NODES];                   // in-degree (clipped at use)
__device__ float g_crystal[N_GRAPHS * H];          // graph pooling accumulator
__device__ float g_gcnt[N_GRAPHS];                 // graph node counts

__device__ __forceinline__ float silu_f(float v) {
    return v / (1.0f + __expf(-v));
}

__device__ __forceinline__ float warp_sum(float s) {
    #pragma unroll
    for (int o = 16; o > 0; o >>= 1) s += __shfl_xor_sync(0xffffffffu, s, o);
    return s;
}

// ---------------- init: zero scratch accumulators ----------------
__global__ void init_zero_kernel() {
    int idx = blockIdx.x * blockDim.x + threadIdx.x;           // grid covers 6.4M exactly
    g_aggr[idx] = 0.0f;
    if (idx < N_GRAPHS * H) g_crystal[idx] = 0.0f;
    if (idx < N_GRAPHS)     g_gcnt[idx] = 0.0f;
    if (idx < N_NODES)      g_cnt[idx] = 0.0f;
}

// ---------------- in-degree count ----------------
__global__ void count_kernel(const int* __restrict__ nbr_idx) {
    int i = blockIdx.x * blockDim.x + threadIdx.x;
    if (i < N_EDGES) atomicAdd(&g_cnt[nbr_idx[2 * i + 1]], 1.0f);
}

// ---------------- node embedding: x = silu(LN(atom @ W + b)) ----------------
__global__ void node_embed_kernel(const float* __restrict__ atom,
                                  const float* __restrict__ W,
                                  const float* __restrict__ bias,
                                  const float* __restrict__ lng,
                                  const float* __restrict__ lnb) {
    int n = blockIdx.x, tid = threadIdx.x;   // 128 threads
    __shared__ float sred[4];
    float4 a = ((const float4*)atom)[n];
    float v = bias[tid] + a.x * W[tid] + a.y * W[H + tid]
                        + a.z * W[2 * H + tid] + a.w * W[3 * H + tid];
    float s = warp_sum(v);
    if ((tid & 31) == 0) sred[tid >> 5] = s;
    __syncthreads();
    float mean = (sred[0] + sred[1] + sred[2] + sred[3]) * (1.0f / H);
    __syncthreads();
    float d = v - mean;
    s = warp_sum(d * d);
    if ((tid & 31) == 0) sred[tid >> 5] = s;
    __syncthreads();
    float var = (sred[0] + sred[1] + sred[2] + sred[3]) * (1.0f / H);
    float y = d * rsqrtf(var + EPS) * lng[tid] + lnb[tid];
    g_x[n * H + tid] = silu_f(y);
}

// ---------------- edge embedding: e = silu(nbr @ W + b), K=41 ----------------
#define EEDGES 32
__global__ void edge_embed_kernel(const float* __restrict__ nbr,
                                  const float* __restrict__ W,
                                  const float* __restrict__ bias) {
    __shared__ float nb[EEDGES * 41];
    int tid = threadIdx.x;                     // 128 threads
    int e0 = blockIdx.x * EEDGES;
    float Wc[41];
    #pragma unroll
    for (int k = 0; k < 41; k++) Wc[k] = W[k * H + tid];
    float b = bias[tid];
    for (int idx = tid; idx < EEDGES * 41; idx += 128)
        nb[idx] = nbr[(size_t)e0 * 41 + idx];
    __syncthreads();
    #pragma unroll 4
    for (int r = 0; r < EEDGES; r++) {
        float acc = b;
        #pragma unroll
        for (int k = 0; k < 41; k++) acc = fmaf(nb[r * 41 + k], Wc[k], acc);
        g_e[(size_t)(e0 + r) * H + tid] = silu_f(acc);
    }
}

// ---------------- fused conv layer ----------------
// Block: 256 threads, tile of 64 edges.
//   m_s  [64][256] : concat(x[src], e)          65536 B
//   h1_s [64][256] : silu(m @ W1 + b1)          65536 B
//   w_s  [32][256] : K-tile of W1 / W2          32768 B
//   dst_s[64]                                     256 B
#define CONV_SMEM (64 * 256 * 4 * 2 + 32 * 256 * 4 + 64 * 4)

__global__ void __launch_bounds__(256, 1)
conv_kernel(const int* __restrict__ nbr_idx,
            const float* __restrict__ W1, const float* __restrict__ b1,
            const float* __restrict__ W2, const float* __restrict__ b2) {
    extern __shared__ float sm[];
    float* m_s  = sm;
    float* h1_s = sm + 64 * 256;
    float* w_s  = sm + 2 * 64 * 256;
    int*   dst_s = (int*)(sm + 2 * 64 * 256 + 32 * 256);

    int tid = threadIdx.x;
    int wid = tid >> 5, lane = tid & 31;
    int e0 = blockIdx.x * 64;

    // ---- gather m = [x[src] | e] ----
    for (int r = wid; r < 64; r += 8) {
        int edge = e0 + r;
        int src = nbr_idx[2 * edge];
        if (lane == 0) dst_s[r] = nbr_idx[2 * edge + 1];
        ((float4*)(m_s + r * 256))[lane] =
            ((const float4*)(g_x + (size_t)src * H))[lane];
        ((float4*)(m_s + r * 256 + 128))[lane] =
            ((const float4*)(g_e + (size_t)edge * H))[lane];
    }
    __syncthreads();

    int tm = tid >> 4;   // 0..15 -> rows tm*4..+3
    int tn = tid & 15;   // 0..15 -> cols tn*16..+15 (stage2) / tn*8..+7 (stage3)

    // ---- stage 2: h1 = silu(m @ W1 + b1), 64x256, K=256 ----
    float acc[4][16];
    #pragma unroll
    for (int i = 0; i < 4; i++)
        #pragma unroll
        for (int j = 0; j < 16; j++) acc[i][j] = 0.0f;

    for (int k0 = 0; k0 < 256; k0 += 32) {
        const float4* wsrc = (const float4*)(W1 + k0 * 256);
        float4* wdst = (float4*)w_s;
        #pragma unroll
        for (int t = 0; t < 8; t++) wdst[tid + t * 256] = wsrc[tid + t * 256];
        __syncthreads();
        #pragma unroll 2
        for (int kk = 0; kk < 32; kk += 4) {
            float4 a4[4];
            #pragma unroll
            for (int i = 0; i < 4; i++)
                a4[i] = *(const float4*)(m_s + (tm * 4 + i) * 256 + k0 + kk);
            #pragma unroll
            for (int q = 0; q < 4; q++) {
                const float* wrow = w_s + (kk + q) * 256 + tn * 16;
                float4 w0 = ((const float4*)wrow)[0];
                float4 w1v = ((const float4*)wrow)[1];
                float4 w2v = ((const float4*)wrow)[2];
                float4 w3v = ((const float4*)wrow)[3];
                float wb[16] = {w0.x, w0.y, w0.z, w0.w,  w1v.x, w1v.y, w1v.z, w1v.w,
                                w2v.x, w2v.y, w2v.z, w2v.w, w3v.x, w3v.y, w3v.z, w3v.w};
                #pragma unroll
                for (int i = 0; i < 4; i++) {
                    float av = ((const float*)&a4[i])[q];
                    #pragma unroll
                    for (int j = 0; j < 16; j++)
                        acc[i][j] = fmaf(av, wb[j], acc[i][j]);
                }
            }
        }
        __syncthreads();
    }
    #pragma unroll
    for (int j = 0; j < 16; j++) {
        float bias = b1[tn * 16 + j];
        #pragma unroll
        for (int i = 0; i < 4; i++)
            h1_s[(tm * 4 + i) * 256 + tn * 16 + j] = silu_f(acc[i][j] + bias);
    }
    __syncthreads();

    // ---- stage 3: h2 = silu(h1 @ W2 + b2), 64x128, K=256 ----
    float acc2[4][8];
    #pragma unroll
    for (int i = 0; i < 4; i++)
        #pragma unroll
        for (int j = 0; j < 8; j++) acc2[i][j] = 0.0f;

    for (int k0 = 0; k0 < 256; k0 += 32) {
        const float4* wsrc = (const float4*)(W2 + k0 * 128);
        float4* wdst = (float4*)w_s;
        #pragma unroll
        for (int t = 0; t < 4; t++) wdst[tid + t * 256] = wsrc[tid + t * 256];
        __syncthreads();
        #pragma unroll 2
        for (int kk = 0; kk < 32; kk += 4) {
            float4 a4[4];
            #pragma unroll
            for (int i = 0; i < 4; i++)
                a4[i] = *(const float4*)(h1_s + (tm * 4 + i) * 256 + k0 + kk);
            #pragma unroll
            for (int q = 0; q < 4; q++) {
                const float* wrow = w_s + (kk + q) * 128 + tn * 8;
                float4 w0 = ((const float4*)wrow)[0];
                float4 w1v = ((const float4*)wrow)[1];
                float wb[8] = {w0.x, w0.y, w0.z, w0.w, w1v.x, w1v.y, w1v.z, w1v.w};
                #pragma unroll
                for (int i = 0; i < 4; i++) {
                    float av = ((const float*)&a4[i])[q];
                    #pragma unroll
                    for (int j = 0; j < 8; j++)
                        acc2[i][j] = fmaf(av, wb[j], acc2[i][j]);
                }
            }
        }
        __syncthreads();
    }

    // ---- epilogue: silu + segment-sum via atomics ----
    #pragma unroll
    for (int i = 0; i < 4; i++) {
        int row = tm * 4 + i;
        int d = dst_s[row];
        float* ap = g_aggr + (size_t)d * H + tn * 8;
        #pragma unroll
        for (int j = 0; j < 8; j++)
            atomicAdd(ap + j, silu_f(acc2[i][j] + b2[tn * 8 + j]));
    }
}

// ---------------- LN update: x = LN(x + aggr/cnt); also re-zero aggr ----------------
__global__ void ln_update_kernel(const float* __restrict__ lng,
                                 const float* __restrict__ lnb) {
    int n = blockIdx.x, tid = threadIdx.x;   // 128 threads
    __shared__ float sred[4];
    float c = g_cnt[n]; c = (c < 1.0f) ? 1.0f : c;
    size_t off = (size_t)n * H + tid;
    float v = g_x[off] + g_aggr[off] / c;
    g_aggr[off] = 0.0f;                      // ready for next layer
    float s = warp_sum(v);
    if ((tid & 31) == 0) sred[tid >> 5] = s;
    __syncthreads();
    float mean = (sred[0] + sred[1] + sred[2] + sred[3]) * (1.0f / H);
    __syncthreads();
    float d = v - mean;
    s = warp_sum(d * d);
    if ((tid & 31) == 0) sred[tid >> 5] = s;
    __syncthreads();
    float var = (sred[0] + sred[1] + sred[2] + sred[3]) * (1.0f / H);
    g_x[off] = d * rsqrtf(var + EPS) * lng[tid] + lnb[tid];
}

// ---------------- graph pooling ----------------
__global__ void pool_kernel(const int* __restrict__ batch_mapping) {
    int n = blockIdx.x, tid = threadIdx.x;   // 128 threads
    int g = batch_mapping[n];
    atomicAdd(&g_crystal[g * H + tid], g_x[(size_t)n * H + tid]);
    if (tid == 0) atomicAdd(&g_gcnt[g], 1.0f);
}

// ---------------- output head ----------------
__global__ void head_kernel(const float* __restrict__ W1, const float* __restrict__ b1,
                            const float* __restrict__ W2, const float* __restrict__ b2,
                            const float* __restrict__ W3, const float* __restrict__ b3,
                            float* __restrict__ out) {
    __shared__ float cs[H], h1[H], h2[64];
    int g = blockIdx.x, tid = threadIdx.x;   // 128 threads
    float gc = g_gcnt[g]; gc = (gc < 1.0f) ? 1.0f : gc;
    cs[tid] = g_crystal[g * H + tid] / gc;
    __syncthreads();
    float acc = b1[tid];
    #pragma unroll 8
    for (int k = 0; k < H; k++) acc = fmaf(cs[k], W1[k * H + tid], acc);
    h1[tid] = silu_f(acc);
    __syncthreads();
    if (tid < 64) {
        acc = b2[tid];
        #pragma unroll 8
        for (int k = 0; k < H; k++) acc = fmaf(h1[k], W2[k * 64 + tid], acc);
        h2[tid] = silu_f(acc);
    }
    __syncthreads();
    if (tid < 3) {
        acc = b3[tid];
        #pragma unroll
        for (int k = 0; k < 64; k++) acc = fmaf(h2[k], W3[k * 3 + tid], acc);
        out[g * 3 + tid] = acc;
    }
}

// ---------------- launch ----------------
extern "C" void kernel_launch(void* const* d_in, const int* in_sizes, int n_in,
                              void* d_out, int out_size) {
    const float* atom_fea  = (const float*)d_in[0];
    const float* nbr_fea   = (const float*)d_in[1];
    const int*   nbr_idx   = (const int*)d_in[2];
    const int*   batch_map = (const int*)d_in[3];
    const float* emb_w     = (const float*)d_in[4];
    const float* emb_b     = (const float*)d_in[5];
    const float* emb_ln_g  = (const float*)d_in[6];
    const float* emb_ln_b  = (const float*)d_in[7];
    const float* edge_w    = (const float*)d_in[8];
    const float* edge_b    = (const float*)d_in[9];
    const float* conv_w1   = (const float*)d_in[10];
    const float* conv_b1   = (const float*)d_in[11];
    const float* conv_w2   = (const float*)d_in[12];
    const float* conv_b2   = (const float*)d_in[13];
    const float* ln_g      = (const float*)d_in[14];
    const float* ln_b      = (const float*)d_in[15];
    const float* out_w1    = (const float*)d_in[16];
    const float* out_b1    = (const float*)d_in[17];
    const float* out_w2    = (const float*)d_in[18];
    const float* out_b2    = (const float*)d_in[19];
    const float* out_w3    = (const float*)d_in[20];
    const float* out_b3    = (const float*)d_in[21];
    float* out = (float*)d_out;

    cudaFuncSetAttribute(conv_kernel,
                         cudaFuncAttributeMaxDynamicSharedMemorySize, CONV_SMEM);

    // zero accumulators (covers aggr/crystal/gcnt/cnt)
    init_zero_kernel<<<(N_NODES * H) / 256, 256>>>();
    count_kernel<<<(N_EDGES + 255) / 256, 256>>>(nbr_idx);
    node_embed_kernel<<<N_NODES, H>>>(atom_fea, emb_w, emb_b, emb_ln_g, emb_ln_b);
    edge_embed_kernel<<<N_EDGES / EEDGES, H>>>(nbr_fea, edge_w, edge_b);

    for (int l = 0; l < NLAYERS; l++) {
        conv_kernel<<<N_EDGES / 64, 256, CONV_SMEM>>>(
            nbr_idx,
            conv_w1 + (size_t)l * 256 * 256, conv_b1 + l * 256,
            conv_w2 + (size_t)l * 256 * 128, conv_b2 + l * 128);
        ln_update_kernel<<<N_NODES, H>>>(ln_g + l * H, ln_b + l * H);
    }

    pool_kernel<<<N_NODES, H>>>(batch_map);
    head_kernel<<<N_GRAPHS, H>>>(out_w1, out_b1, out_w2, out_b2, out_w3, out_b3, out);
}

// round 7
// speedup vs baseline: 1.6891x; 1.6891x over previous
#include <cuda_runtime.h>
#include <cstddef>

#define N_NODES  50000
#define N_EDGES  800000
#define N_GRAPHS 1024
#define H        128
#define NLAYERS  5
#define EPS      1e-5f

// ---------------- device scratch (static globals; no allocation) ----------------
__device__ float g_x[N_NODES * H];                 // node features (25.6 MB)
__device__ float g_e[(size_t)N_EDGES * H];         // edge features (409.6 MB)
__device__ float g_aggr[N_NODES * H];              // per-layer aggregation (25.6 MB)
__device__ float g_xw[(size_t)N_NODES * 2 * H];    // P = x @ W1_top per node (51.2 MB)
__device__ float g_cnt[N_NODES];                   // in-degree (clipped at use)
__device__ float g_crystal[N_GRAPHS * H];          // graph pooling accumulator
__device__ float g_gcnt[N_GRAPHS];                 // graph node counts

__device__ __forceinline__ float silu_f(float v) {
    return v / (1.0f + __expf(-v));
}

__device__ __forceinline__ float warp_sum(float s) {
    #pragma unroll
    for (int o = 16; o > 0; o >>= 1) s += __shfl_xor_sync(0xffffffffu, s, o);
    return s;
}

// ---------------- init: zero scratch accumulators ----------------
__global__ void init_zero_kernel() {
    int idx = blockIdx.x * blockDim.x + threadIdx.x;           // grid covers 6.4M exactly
    g_aggr[idx] = 0.0f;
    if (idx < N_GRAPHS * H) g_crystal[idx] = 0.0f;
    if (idx < N_GRAPHS)     g_gcnt[idx] = 0.0f;
    if (idx < N_NODES)      g_cnt[idx] = 0.0f;
}

// ---------------- in-degree count ----------------
__global__ void count_kernel(const int* __restrict__ nbr_idx) {
    int i = blockIdx.x * blockDim.x + threadIdx.x;
    if (i < N_EDGES) atomicAdd(&g_cnt[nbr_idx[2 * i + 1]], 1.0f);
}

// ---------------- node embedding: x = silu(LN(atom @ W + b)) ----------------
__global__ void node_embed_kernel(const float* __restrict__ atom,
                                  const float* __restrict__ W,
                                  const float* __restrict__ bias,
                                  const float* __restrict__ lng,
                                  const float* __restrict__ lnb) {
    int n = blockIdx.x, tid = threadIdx.x;   // 128 threads
    __shared__ float sred[4];
    float4 a = ((const float4*)atom)[n];
    float v = bias[tid] + a.x * W[tid] + a.y * W[H + tid]
                        + a.z * W[2 * H + tid] + a.w * W[3 * H + tid];
    float s = warp_sum(v);
    if ((tid & 31) == 0) sred[tid >> 5] = s;
    __syncthreads();
    float mean = (sred[0] + sred[1] + sred[2] + sred[3]) * (1.0f / H);
    __syncthreads();
    float d = v - mean;
    s = warp_sum(d * d);
    if ((tid & 31) == 0) sred[tid >> 5] = s;
    __syncthreads();
    float var = (sred[0] + sred[1] + sred[2] + sred[3]) * (1.0f / H);
    float y = d * rsqrtf(var + EPS) * lng[tid] + lnb[tid];
    g_x[n * H + tid] = silu_f(y);
}

// ---------------- edge embedding: e = silu(nbr @ W + b), K=41 ----------------
#define EEDGES 32
__global__ void edge_embed_kernel(const float* __restrict__ nbr,
                                  const float* __restrict__ W,
                                  const float* __restrict__ bias) {
    __shared__ float nb[EEDGES * 41];
    int tid = threadIdx.x;                     // 128 threads
    int e0 = blockIdx.x * EEDGES;
    float Wc[41];
    #pragma unroll
    for (int k = 0; k < 41; k++) Wc[k] = W[k * H + tid];
    float b = bias[tid];
    for (int idx = tid; idx < EEDGES * 41; idx += 128)
        nb[idx] = nbr[(size_t)e0 * 41 + idx];
    __syncthreads();
    #pragma unroll 4
    for (int r = 0; r < EEDGES; r++) {
        float acc = b;
        #pragma unroll
        for (int k = 0; k < 41; k++) acc = fmaf(nb[r * 41 + k], Wc[k], acc);
        g_e[(size_t)(e0 + r) * H + tid] = silu_f(acc);
    }
}

// ---------------- per-node precompute: P = x @ W1[0:128, :]  (50000 x 256) ----------------
// Block: 256 threads, tile of 64 nodes. K = 128.
#define XW_SMEM (64 * 128 * 4 + 16 * 256 * 4)   // 48 KB: x_s + w_s

__global__ void __launch_bounds__(256, 2)
xw_kernel(const float* __restrict__ W1) {
    extern __shared__ float sm[];
    float* x_s = sm;               // [64][128]
    float* w_s = sm + 64 * 128;    // [16][256]

    int tid = threadIdx.x;
    int wid = tid >> 5, lane = tid & 31;
    int n0 = blockIdx.x * 64;

    // gather 64 node rows (sequential)
    for (int r = wid; r < 64; r += 8) {
        int node = n0 + r;
        int nsafe = (node < N_NODES) ? node : 0;
        ((float4*)(x_s + r * 128))[lane] =
            ((const float4*)(g_x + (size_t)nsafe * H))[lane];
    }
    __syncthreads();

    int tm = tid >> 4;   // 0..15 -> rows tm*4..+3
    int tn = tid & 15;   // 0..15 -> cols tn*16..+15

    float acc[4][16];
    #pragma unroll
    for (int i = 0; i < 4; i++)
        #pragma unroll
        for (int j = 0; j < 16; j++) acc[i][j] = 0.0f;

    for (int k0 = 0; k0 < 128; k0 += 16) {
        const float4* wsrc = (const float4*)(W1 + (size_t)k0 * 256);
        float4* wdst = (float4*)w_s;
        #pragma unroll
        for (int t = 0; t < 4; t++) wdst[tid + t * 256] = wsrc[tid + t * 256];
        __syncthreads();
        #pragma unroll
        for (int kk = 0; kk < 16; kk += 4) {
            float4 a4[4];
            #pragma unroll
            for (int i = 0; i < 4; i++)
                a4[i] = *(const float4*)(x_s + (tm * 4 + i) * 128 + k0 + kk);
            #pragma unroll
            for (int q = 0; q < 4; q++) {
                const float* wrow = w_s + (kk + q) * 256 + tn * 16;
                float4 w0 = ((const float4*)wrow)[0];
                float4 w1v = ((const float4*)wrow)[1];
                float4 w2v = ((const float4*)wrow)[2];
                float4 w3v = ((const float4*)wrow)[3];
                float wb[16] = {w0.x, w0.y, w0.z, w0.w,  w1v.x, w1v.y, w1v.z, w1v.w,
                                w2v.x, w2v.y, w2v.z, w2v.w, w3v.x, w3v.y, w3v.z, w3v.w};
                #pragma unroll
                for (int i = 0; i < 4; i++) {
                    float av = ((const float*)&a4[i])[q];
                    #pragma unroll
                    for (int j = 0; j < 16; j++)
                        acc[i][j] = fmaf(av, wb[j], acc[i][j]);
                }
            }
        }
        __syncthreads();
    }

    #pragma unroll
    for (int i = 0; i < 4; i++) {
        int node = n0 + tm * 4 + i;
        if (node < N_NODES) {
            float* dst = g_xw + (size_t)node * 256 + tn * 16;
            #pragma unroll
            for (int j = 0; j < 16; j++) dst[j] = acc[i][j];
        }
    }
}

// ---------------- fused conv layer ----------------
// Block: 256 threads, tile of 64 edges, 2 CTAs/SM.
//   h1_s [64][256] : gathered P[src]; then silu(P + e@W1_bot + b1)   65536 B
//   e_s  [64][128] : e tile                                          32768 B
//   w_s  [16][256] : K-tile of W1_bot / W2                           16384 B
//   dst_s[64]                                                          256 B
#define CONV_SMEM (64 * 256 * 4 + 64 * 128 * 4 + 16 * 256 * 4 + 64 * 4)

__global__ void __launch_bounds__(256, 2)
conv_kernel(const int* __restrict__ nbr_idx,
            const float* __restrict__ W1, const float* __restrict__ b1,
            const float* __restrict__ W2, const float* __restrict__ b2) {
    extern __shared__ float sm[];
    float* h1_s = sm;                              // [64][256]
    float* e_s  = sm + 64 * 256;                   // [64][128]
    float* w_s  = sm + 64 * 256 + 64 * 128;        // [16][256]
    int*   dst_s = (int*)(w_s + 16 * 256);

    int tid = threadIdx.x;
    int wid = tid >> 5, lane = tid & 31;
    int e0 = blockIdx.x * 64;

    // ---- gather: h1_s <- P[src] (partial GEMM1), e_s <- e tile ----
    for (int r = wid; r < 64; r += 8) {
        int edge = e0 + r;
        int src = nbr_idx[2 * edge];
        if (lane == 0) dst_s[r] = nbr_idx[2 * edge + 1];
        const float4* psrc = (const float4*)(g_xw + (size_t)src * 256);
        ((float4*)(h1_s + r * 256))[lane]      = psrc[lane];
        ((float4*)(h1_s + r * 256))[lane + 32] = psrc[lane + 32];
        ((float4*)(e_s + r * 128))[lane] =
            ((const float4*)(g_e + (size_t)edge * H))[lane];
    }
    __syncthreads();

    int tm = tid >> 4;   // rows tm*4..+3
    int tn = tid & 15;   // cols tn*16..+15 (stage2) / tn*8..+7 (stage3)

    // ---- stage 2: h1 = silu(P + e @ W1_bot + b1), 64x256, K=128 ----
    float acc[4][16];
    #pragma unroll
    for (int i = 0; i < 4; i++)
        #pragma unroll
        for (int j = 0; j < 16; j++) acc[i][j] = 0.0f;

    for (int k0 = 0; k0 < 128; k0 += 16) {
        // W1_bot rows 128..255
        const float4* wsrc = (const float4*)(W1 + (size_t)(128 + k0) * 256);
        float4* wdst = (float4*)w_s;
        #pragma unroll
        for (int t = 0; t < 4; t++) wdst[tid + t * 256] = wsrc[tid + t * 256];
        __syncthreads();
        #pragma unroll
        for (int kk = 0; kk < 16; kk += 4) {
            float4 a4[4];
            #pragma unroll
            for (int i = 0; i < 4; i++)
                a4[i] = *(const float4*)(e_s + (tm * 4 + i) * 128 + k0 + kk);
            #pragma unroll
            for (int q = 0; q < 4; q++) {
                const float* wrow = w_s + (kk + q) * 256 + tn * 16;
                float4 w0 = ((const float4*)wrow)[0];
                float4 w1v = ((const float4*)wrow)[1];
                float4 w2v = ((const float4*)wrow)[2];
                float4 w3v = ((const float4*)wrow)[3];
                float wb[16] = {w0.x, w0.y, w0.z, w0.w,  w1v.x, w1v.y, w1v.z, w1v.w,
                                w2v.x, w2v.y, w2v.z, w2v.w, w3v.x, w3v.y, w3v.z, w3v.w};
                #pragma unroll
                for (int i = 0; i < 4; i++) {
                    float av = ((const float*)&a4[i])[q];
                    #pragma unroll
                    for (int j = 0; j < 16; j++)
                        acc[i][j] = fmaf(av, wb[j], acc[i][j]);
                }
            }
        }
        __syncthreads();
    }

    // epilogue: each thread owns its h1_s elements (read P, add, silu, write back)
    #pragma unroll
    for (int j = 0; j < 16; j++) {
        float bias = b1[tn * 16 + j];
        #pragma unroll
        for (int i = 0; i < 4; i++) {
            float* slot = h1_s + (tm * 4 + i) * 256 + tn * 16 + j;
            *slot = silu_f(acc[i][j] + bias + *slot);
        }
    }
    __syncthreads();

    // ---- stage 3: h2 = silu(h1 @ W2 + b2), 64x128, K=256 ----
    float acc2[4][8];
    #pragma unroll
    for (int i = 0; i < 4; i++)
        #pragma unroll
        for (int j = 0; j < 8; j++) acc2[i][j] = 0.0f;

    for (int k0 = 0; k0 < 256; k0 += 16) {
        const float4* wsrc = (const float4*)(W2 + (size_t)k0 * 128);
        float4* wdst = (float4*)w_s;
        #pragma unroll
        for (int t = 0; t < 2; t++) wdst[tid + t * 256] = wsrc[tid + t * 256];
        __syncthreads();
        #pragma unroll
        for (int kk = 0; kk < 16; kk += 4) {
            float4 a4[4];
            #pragma unroll
            for (int i = 0; i < 4; i++)
                a4[i] = *(const float4*)(h1_s + (tm * 4 + i) * 256 + k0 + kk);
            #pragma unroll
            for (int q = 0; q < 4; q++) {
                const float* wrow = w_s + (kk + q) * 128 + tn * 8;
                float4 w0 = ((const float4*)wrow)[0];
                float4 w1v = ((const float4*)wrow)[1];
                float wb[8] = {w0.x, w0.y, w0.z, w0.w, w1v.x, w1v.y, w1v.z, w1v.w};
                #pragma unroll
                for (int i = 0; i < 4; i++) {
                    float av = ((const float*)&a4[i])[q];
                    #pragma unroll
                    for (int j = 0; j < 8; j++)
                        acc2[i][j] = fmaf(av, wb[j], acc2[i][j]);
                }
            }
        }
        __syncthreads();
    }

    // ---- epilogue: silu + segment-sum via vector atomics ----
    float b2r[8];
    #pragma unroll
    for (int j = 0; j < 8; j++) b2r[j] = b2[tn * 8 + j];
    #pragma unroll
    for (int i = 0; i < 4; i++) {
        int row = tm * 4 + i;
        int d = dst_s[row];
        float* ap = g_aggr + (size_t)d * H + tn * 8;
        float4 v0, v1;
        v0.x = silu_f(acc2[i][0] + b2r[0]);
        v0.y = silu_f(acc2[i][1] + b2r[1]);
        v0.z = silu_f(acc2[i][2] + b2r[2]);
        v0.w = silu_f(acc2[i][3] + b2r[3]);
        v1.x = silu_f(acc2[i][4] + b2r[4]);
        v1.y = silu_f(acc2[i][5] + b2r[5]);
        v1.z = silu_f(acc2[i][6] + b2r[6]);
        v1.w = silu_f(acc2[i][7] + b2r[7]);
#if __CUDA_ARCH__ >= 900
        atomicAdd((float4*)ap, v0);
        atomicAdd((float4*)(ap + 4), v1);
#else
        atomicAdd(ap + 0, v0.x); atomicAdd(ap + 1, v0.y);
        atomicAdd(ap + 2, v0.z); atomicAdd(ap + 3, v0.w);
        atomicAdd(ap + 4, v1.x); atomicAdd(ap + 5, v1.y);
        atomicAdd(ap + 6, v1.z); atomicAdd(ap + 7, v1.w);
#endif
    }
}

// ---------------- LN update: x = LN(x + aggr/cnt); also re-zero aggr ----------------
__global__ void ln_update_kernel(const float* __restrict__ lng,
                                 const float* __restrict__ lnb) {
    int n = blockIdx.x, tid = threadIdx.x;   // 128 threads
    __shared__ float sred[4];
    float c = g_cnt[n]; c = (c < 1.0f) ? 1.0f : c;
    size_t off = (size_t)n * H + tid;
    float v = g_x[off] + g_aggr[off] / c;
    g_aggr[off] = 0.0f;                      // ready for next layer
    float s = warp_sum(v);
    if ((tid & 31) == 0) sred[tid >> 5] = s;
    __syncthreads();
    float mean = (sred[0] + sred[1] + sred[2] + sred[3]) * (1.0f / H);
    __syncthreads();
    float d = v - mean;
    s = warp_sum(d * d);
    if ((tid & 31) == 0) sred[tid >> 5] = s;
    __syncthreads();
    float var = (sred[0] + sred[1] + sred[2] + sred[3]) * (1.0f / H);
    g_x[off] = d * rsqrtf(var + EPS) * lng[tid] + lnb[tid];
}

// ---------------- graph pooling ----------------
__global__ void pool_kernel(const int* __restrict__ batch_mapping) {
    int n = blockIdx.x, tid = threadIdx.x;   // 128 threads
    int g = batch_mapping[n];
    atomicAdd(&g_crystal[g * H + tid], g_x[(size_t)n * H + tid]);
    if (tid == 0) atomicAdd(&g_gcnt[g], 1.0f);
}

// ---------------- output head ----------------
__global__ void head_kernel(const float* __restrict__ W1, const float* __restrict__ b1,
                            const float* __restrict__ W2, const float* __restrict__ b2,
                            const float* __restrict__ W3, const float* __restrict__ b3,
                            float* __restrict__ out) {
    __shared__ float cs[H], h1[H], h2[64];
    int g = blockIdx.x, tid = threadIdx.x;   // 128 threads
    float gc = g_gcnt[g]; gc = (gc < 1.0f) ? 1.0f : gc;
    cs[tid] = g_crystal[g * H + tid] / gc;
    __syncthreads();
    float acc = b1[tid];
    #pragma unroll 8
    for (int k = 0; k < H; k++) acc = fmaf(cs[k], W1[k * H + tid], acc);
    h1[tid] = silu_f(acc);
    __syncthreads();
    if (tid < 64) {
        acc = b2[tid];
        #pragma unroll 8
        for (int k = 0; k < H; k++) acc = fmaf(h1[k], W2[k * 64 + tid], acc);
        h2[tid] = silu_f(acc);
    }
    __syncthreads();
    if (tid < 3) {
        acc = b3[tid];
        #pragma unroll
        for (int k = 0; k < 64; k++) acc = fmaf(h2[k], W3[k * 3 + tid], acc);
        out[g * 3 + tid] = acc;
    }
}

// ---------------- launch ----------------
extern "C" void kernel_launch(void* const* d_in, const int* in_sizes, int n_in,
                              void* d_out, int out_size) {
    const float* atom_fea  = (const float*)d_in[0];
    const float* nbr_fea   = (const float*)d_in[1];
    const int*   nbr_idx   = (const int*)d_in[2];
    const int*   batch_map = (const int*)d_in[3];
    const float* emb_w     = (const float*)d_in[4];
    const float* emb_b     = (const float*)d_in[5];
    const float* emb_ln_g  = (const float*)d_in[6];
    const float* emb_ln_b  = (const float*)d_in[7];
    const float* edge_w    = (const float*)d_in[8];
    const float* edge_b    = (const float*)d_in[9];
    const float* conv_w1   = (const float*)d_in[10];
    const float* conv_b1   = (const float*)d_in[11];
    const float* conv_w2   = (const float*)d_in[12];
    const float* conv_b2   = (const float*)d_in[13];
    const float* ln_g      = (const float*)d_in[14];
    const float* ln_b      = (const float*)d_in[15];
    const float* out_w1    = (const float*)d_in[16];
    const float* out_b1    = (const float*)d_in[17];
    const float* out_w2    = (const float*)d_in[18];
    const float* out_b2    = (const float*)d_in[19];
    const float* out_w3    = (const float*)d_in[20];
    const float* out_b3    = (const float*)d_in[21];
    float* out = (float*)d_out;

    cudaFuncSetAttribute(conv_kernel,
                         cudaFuncAttributeMaxDynamicSharedMemorySize, CONV_SMEM);
    cudaFuncSetAttribute(xw_kernel,
                         cudaFuncAttributeMaxDynamicSharedMemorySize, XW_SMEM);

    // zero accumulators (covers aggr/crystal/gcnt/cnt)
    init_zero_kernel<<<(N_NODES * H) / 256, 256>>>();
    count_kernel<<<(N_EDGES + 255) / 256, 256>>>(nbr_idx);
    node_embed_kernel<<<N_NODES, H>>>(atom_fea, emb_w, emb_b, emb_ln_g, emb_ln_b);
    edge_embed_kernel<<<N_EDGES / EEDGES, H>>>(nbr_fea, edge_w, edge_b);

    for (int l = 0; l < NLAYERS; l++) {
        const float* W1 = conv_w1 + (size_t)l * 256 * 256;
        xw_kernel<<<(N_NODES + 63) / 64, 256, XW_SMEM>>>(W1);
        conv_kernel<<<N_EDGES / 64, 256, CONV_SMEM>>>(
            nbr_idx,
            W1, conv_b1 + l * 256,
            conv_w2 + (size_t)l * 256 * 128, conv_b2 + l * 128);
        ln_update_kernel<<<N_NODES, H>>>(ln_g + l * H, ln_b + l * H);
    }

    pool_kernel<<<N_NODES, H>>>(batch_map);
    head_kernel<<<N_GRAPHS, H>>>(out_w1, out_b1, out_w2, out_b2, out_w3, out_b3, out);
}

// round 8
// speedup vs baseline: 4.9502x; 2.9307x over previous
#include <cuda_runtime.h>
#include <cstddef>
#include <cstdint>

#define N_NODES  50000
#define N_EDGES  800000
#define N_GRAPHS 1024
#define H        128
#define NLAYERS  5
#define EPS      1e-5f

// ---------------- device scratch (static globals; no allocation) ----------------
__device__ float g_x[N_NODES * H];                 // node features (25.6 MB)
__device__ float g_e[(size_t)N_EDGES * H];         // edge features (409.6 MB)
__device__ float g_aggr[N_NODES * H];              // per-layer aggregation (25.6 MB)
__device__ float g_xw[(size_t)N_NODES * 2 * H];    // P = x @ W1_top per node (51.2 MB)
__device__ float g_cnt[N_NODES];                   // in-degree (clipped at use)
__device__ float g_crystal[N_GRAPHS * H];          // graph pooling accumulator
__device__ float g_gcnt[N_GRAPHS];                 // graph node counts

__device__ __forceinline__ float silu_f(float v) {
    return v / (1.0f + __expf(-v));
}

__device__ __forceinline__ float warp_sum(float s) {
    #pragma unroll
    for (int o = 16; o > 0; o >>= 1) s += __shfl_xor_sync(0xffffffffu, s, o);
    return s;
}

// round f32 -> tf32 (round-to-nearest), result as f32 bit pattern
__device__ __forceinline__ float f2tf(float f) {
    uint32_t u;
    asm("cvt.rna.tf32.f32 %0, %1;" : "=r"(u) : "f"(f));
    return __uint_as_float(u);
}

__device__ __forceinline__ void mma_tf32(float c[4],
                                         uint32_t a0, uint32_t a1, uint32_t a2, uint32_t a3,
                                         uint32_t b0, uint32_t b1) {
    asm volatile(
        "mma.sync.aligned.m16n8k8.row.col.f32.tf32.tf32.f32 "
        "{%0,%1,%2,%3}, {%4,%5,%6,%7}, {%8,%9}, {%0,%1,%2,%3};\n"
        : "+f"(c[0]), "+f"(c[1]), "+f"(c[2]), "+f"(c[3])
        : "r"(a0), "r"(a1), "r"(a2), "r"(a3), "r"(b0), "r"(b1));
}

// ---------------- init: zero scratch accumulators ----------------
__global__ void init_zero_kernel() {
    int idx = blockIdx.x * blockDim.x + threadIdx.x;           // grid covers 6.4M exactly
    g_aggr[idx] = 0.0f;
    if (idx < N_GRAPHS * H) g_crystal[idx] = 0.0f;
    if (idx < N_GRAPHS)     g_gcnt[idx] = 0.0f;
    if (idx < N_NODES)      g_cnt[idx] = 0.0f;
}

// ---------------- in-degree count ----------------
__global__ void count_kernel(const int* __restrict__ nbr_idx) {
    int i = blockIdx.x * blockDim.x + threadIdx.x;
    if (i < N_EDGES) atomicAdd(&g_cnt[nbr_idx[2 * i + 1]], 1.0f);
}

// ---------------- node embedding: x = silu(LN(atom @ W + b)) ----------------
__global__ void node_embed_kernel(const float* __restrict__ atom,
                                  const float* __restrict__ W,
                                  const float* __restrict__ bias,
                                  const float* __restrict__ lng,
                                  const float* __restrict__ lnb) {
    int n = blockIdx.x, tid = threadIdx.x;   // 128 threads
    __shared__ float sred[4];
    float4 a = ((const float4*)atom)[n];
    float v = bias[tid] + a.x * W[tid] + a.y * W[H + tid]
                        + a.z * W[2 * H + tid] + a.w * W[3 * H + tid];
    float s = warp_sum(v);
    if ((tid & 31) == 0) sred[tid >> 5] = s;
    __syncthreads();
    float mean = (sred[0] + sred[1] + sred[2] + sred[3]) * (1.0f / H);
    __syncthreads();
    float d = v - mean;
    s = warp_sum(d * d);
    if ((tid & 31) == 0) sred[tid >> 5] = s;
    __syncthreads();
    float var = (sred[0] + sred[1] + sred[2] + sred[3]) * (1.0f / H);
    float y = d * rsqrtf(var + EPS) * lng[tid] + lnb[tid];
    g_x[n * H + tid] = silu_f(y);
}

// ---------------- edge embedding: e = silu(nbr @ W + b), K=41 ----------------
#define EEDGES 32
__global__ void edge_embed_kernel(const float* __restrict__ nbr,
                                  const float* __restrict__ W,
                                  const float* __restrict__ bias) {
    __shared__ float nb[EEDGES * 41];
    int tid = threadIdx.x;                     // 128 threads
    int e0 = blockIdx.x * EEDGES;
    float Wc[41];
    #pragma unroll
    for (int k = 0; k < 41; k++) Wc[k] = W[k * H + tid];
    float b = bias[tid];
    for (int idx = tid; idx < EEDGES * 41; idx += 128)
        nb[idx] = nbr[(size_t)e0 * 41 + idx];
    __syncthreads();
    #pragma unroll 4
    for (int r = 0; r < EEDGES; r++) {
        float acc = b;
        #pragma unroll
        for (int k = 0; k < 41; k++) acc = fmaf(nb[r * 41 + k], Wc[k], acc);
        g_e[(size_t)(e0 + r) * H + tid] = silu_f(acc);
    }
}

// ---------------- per-node precompute: P = x @ W1[0:128, :]  (50000 x 256) ----------------
// fp32 (keeps the residual-path precision). Block: 256 threads, tile of 64 nodes.
#define XW_SMEM (64 * 128 * 4 + 16 * 256 * 4)   // 48 KB

__global__ void __launch_bounds__(256, 2)
xw_kernel(const float* __restrict__ W1) {
    extern __shared__ float sm[];
    float* x_s = sm;               // [64][128]
    float* w_s = sm + 64 * 128;    // [16][256]

    int tid = threadIdx.x;
    int wid = tid >> 5, lane = tid & 31;
    int n0 = blockIdx.x * 64;

    for (int r = wid; r < 64; r += 8) {
        int node = n0 + r;
        int nsafe = (node < N_NODES) ? node : 0;
        ((float4*)(x_s + r * 128))[lane] =
            ((const float4*)(g_x + (size_t)nsafe * H))[lane];
    }
    __syncthreads();

    int tm = tid >> 4;
    int tn = tid & 15;

    float acc[4][16];
    #pragma unroll
    for (int i = 0; i < 4; i++)
        #pragma unroll
        for (int j = 0; j < 16; j++) acc[i][j] = 0.0f;

    for (int k0 = 0; k0 < 128; k0 += 16) {
        const float4* wsrc = (const float4*)(W1 + (size_t)k0 * 256);
        float4* wdst = (float4*)w_s;
        #pragma unroll
        for (int t = 0; t < 4; t++) wdst[tid + t * 256] = wsrc[tid + t * 256];
        __syncthreads();
        #pragma unroll
        for (int kk = 0; kk < 16; kk += 4) {
            float4 a4[4];
            #pragma unroll
            for (int i = 0; i < 4; i++)
                a4[i] = *(const float4*)(x_s + (tm * 4 + i) * 128 + k0 + kk);
            #pragma unroll
            for (int q = 0; q < 4; q++) {
                const float* wrow = w_s + (kk + q) * 256 + tn * 16;
                float4 w0 = ((const float4*)wrow)[0];
                float4 w1v = ((const float4*)wrow)[1];
                float4 w2v = ((const float4*)wrow)[2];
                float4 w3v = ((const float4*)wrow)[3];
                float wb[16] = {w0.x, w0.y, w0.z, w0.w,  w1v.x, w1v.y, w1v.z, w1v.w,
                                w2v.x, w2v.y, w2v.z, w2v.w, w3v.x, w3v.y, w3v.z, w3v.w};
                #pragma unroll
                for (int i = 0; i < 4; i++) {
                    float av = ((const float*)&a4[i])[q];
                    #pragma unroll
                    for (int j = 0; j < 16; j++)
                        acc[i][j] = fmaf(av, wb[j], acc[i][j]);
                }
            }
        }
        __syncthreads();
    }

    #pragma unroll
    for (int i = 0; i < 4; i++) {
        int node = n0 + tm * 4 + i;
        if (node < N_NODES) {
            float* dst = g_xw + (size_t)node * 256 + tn * 16;
            #pragma unroll
            for (int j = 0; j < 16; j++) dst[j] = acc[i][j];
        }
    }
}

// ---------------- fused conv layer, tf32 tensor-core version ----------------
// Block: 512 threads (16 warps), tile of 128 edges, 1 CTA/SM.
// smem (padded strides chosen for conflict-free mma-fragment LDS):
//   e_s  [128][132] : e tile (tf32-rounded)                     67584 B
//   h1_s [128][260] : P[src] gather; then h1 (tf32-rounded)    133120 B
//   w_s  [16][264]  : K-tile of W1_bot (stage2) / W2 [16][136]  16896 B
//   dst_s[128]                                                    512 B
#define ES 132
#define HS 260
#define WS2 264
#define WS3 136
#define CONV_SMEM (128 * ES * 4 + 128 * HS * 4 + 16 * WS2 * 4 + 128 * 4)

__global__ void __launch_bounds__(512, 1)
conv_kernel(const int* __restrict__ nbr_idx,
            const float* __restrict__ W1, const float* __restrict__ b1,
            const float* __restrict__ W2, const float* __restrict__ b2) {
    extern __shared__ float sm[];
    float* e_s  = sm;                                // [128][132]
    float* h1_s = sm + 128 * ES;                     // [128][260]
    float* w_s  = sm + 128 * ES + 128 * HS;          // [16][264]
    int*   dst_s = (int*)(w_s + 16 * WS2);

    int tid  = threadIdx.x;
    int wid  = tid >> 5, lane = tid & 31;
    int lq   = lane >> 2;          // lane/4 : 0..7
    int lr   = lane & 3;           // lane%4 : 0..3
    int e0   = blockIdx.x * 128;

    // ---- gather: h1_s <- P[src] (fp32), e_s <- tf32(e) ----
    for (int r = wid; r < 128; r += 16) {
        int edge = e0 + r;
        int src = nbr_idx[2 * edge];
        if (lane == 0) dst_s[r] = nbr_idx[2 * edge + 1];
        const float4* psrc = (const float4*)(g_xw + (size_t)src * 256);
        *(float4*)(h1_s + r * HS + lane * 4)       = psrc[lane];
        *(float4*)(h1_s + r * HS + 128 + lane * 4) = psrc[lane + 32];
        float4 ev = ((const float4*)(g_e + (size_t)edge * H))[lane];
        float4 et;
        et.x = f2tf(ev.x); et.y = f2tf(ev.y); et.z = f2tf(ev.z); et.w = f2tf(ev.w);
        *(float4*)(e_s + r * ES + lane * 4) = et;
    }
    __syncthreads();

    // ---- stage 2: h1 = silu(P + e @ W1_bot + b1), 128x256, K=128 ----
    {
        int wm = wid >> 2;     // 0..3 -> rows wm*32
        int wn = wid & 3;      // 0..3 -> cols wn*64
        float c[2][8][4];
        #pragma unroll
        for (int mi = 0; mi < 2; mi++)
            #pragma unroll
            for (int ni = 0; ni < 8; ni++)
                #pragma unroll
                for (int q = 0; q < 4; q++) c[mi][ni][q] = 0.0f;

        for (int kt = 0; kt < 128; kt += 16) {
            // stage tf32(W1_bot rows kt..kt+15)
            {
                int row = tid >> 5;
                int col = (tid & 31) * 8;
                const float* src = W1 + (size_t)(128 + kt + row) * 256 + col;
                float4 v0 = ((const float4*)src)[0];
                float4 v1 = ((const float4*)src)[1];
                float4 t0, t1;
                t0.x = f2tf(v0.x); t0.y = f2tf(v0.y); t0.z = f2tf(v0.z); t0.w = f2tf(v0.w);
                t1.x = f2tf(v1.x); t1.y = f2tf(v1.y); t1.z = f2tf(v1.z); t1.w = f2tf(v1.w);
                *(float4*)(w_s + row * WS2 + col)     = t0;
                *(float4*)(w_s + row * WS2 + col + 4) = t1;
            }
            __syncthreads();
            #pragma unroll
            for (int k8 = 0; k8 < 2; k8++) {
                int kk = kt + k8 * 8;
                uint32_t a[2][4];
                #pragma unroll
                for (int mi = 0; mi < 2; mi++) {
                    const float* ab = e_s + (wm * 32 + mi * 16 + lq) * ES + kk + lr;
                    a[mi][0] = __float_as_uint(ab[0]);
                    a[mi][1] = __float_as_uint(ab[8 * ES]);
                    a[mi][2] = __float_as_uint(ab[4]);
                    a[mi][3] = __float_as_uint(ab[8 * ES + 4]);
                }
                #pragma unroll
                for (int ni = 0; ni < 8; ni++) {
                    const float* bb = w_s + (k8 * 8 + lr) * WS2 + wn * 64 + ni * 8 + lq;
                    uint32_t b0 = __float_as_uint(bb[0]);
                    uint32_t b1v = __float_as_uint(bb[4 * WS2]);
                    #pragma unroll
                    for (int mi = 0; mi < 2; mi++)
                        mma_tf32(c[mi][ni], a[mi][0], a[mi][1], a[mi][2], a[mi][3], b0, b1v);
                }
            }
            __syncthreads();
        }

        // epilogue: h1 = tf32(silu(P + acc + bias)), written back into h1_s
        #pragma unroll
        for (int mi = 0; mi < 2; mi++) {
            #pragma unroll
            for (int ni = 0; ni < 8; ni++) {
                int row0 = wm * 32 + mi * 16 + lq;
                int col  = wn * 64 + ni * 8 + lr * 2;
                float bias0 = __ldg(b1 + col), bias1 = __ldg(b1 + col + 1);
                float* s0 = h1_s + row0 * HS + col;
                s0[0] = f2tf(silu_f(c[mi][ni][0] + bias0 + s0[0]));
                s0[1] = f2tf(silu_f(c[mi][ni][1] + bias1 + s0[1]));
                float* s2 = s0 + 8 * HS;
                s2[0] = f2tf(silu_f(c[mi][ni][2] + bias0 + s2[0]));
                s2[1] = f2tf(silu_f(c[mi][ni][3] + bias1 + s2[1]));
            }
        }
    }
    __syncthreads();

    // ---- stage 3: h2 = silu(h1 @ W2 + b2), 128x128, K=256; scatter-add ----
    {
        int wm = wid >> 2;     // rows wm*32
        int wn = wid & 3;      // cols wn*32
        float c[2][4][4];
        #pragma unroll
        for (int mi = 0; mi < 2; mi++)
            #pragma unroll
            for (int ni = 0; ni < 4; ni++)
                #pragma unroll
                for (int q = 0; q < 4; q++) c[mi][ni][q] = 0.0f;

        for (int kt = 0; kt < 256; kt += 16) {
            // stage tf32(W2 rows kt..kt+15)
            {
                int row = tid >> 5;
                int col = (tid & 31) * 4;
                const float* src = W2 + (size_t)(kt + row) * 128 + col;
                float4 v = *(const float4*)src;
                float4 t;
                t.x = f2tf(v.x); t.y = f2tf(v.y); t.z = f2tf(v.z); t.w = f2tf(v.w);
                *(float4*)(w_s + row * WS3 + col) = t;
            }
            __syncthreads();
            #pragma unroll
            for (int k8 = 0; k8 < 2; k8++) {
                int kk = kt + k8 * 8;
                uint32_t a[2][4];
                #pragma unroll
                for (int mi = 0; mi < 2; mi++) {
                    const float* ab = h1_s + (wm * 32 + mi * 16 + lq) * HS + kk + lr;
                    a[mi][0] = __float_as_uint(ab[0]);
                    a[mi][1] = __float_as_uint(ab[8 * HS]);
                    a[mi][2] = __float_as_uint(ab[4]);
                    a[mi][3] = __float_as_uint(ab[8 * HS + 4]);
                }
                #pragma unroll
                for (int ni = 0; ni < 4; ni++) {
                    const float* bb = w_s + (k8 * 8 + lr) * WS3 + wn * 32 + ni * 8 + lq;
                    uint32_t b0 = __float_as_uint(bb[0]);
                    uint32_t b1v = __float_as_uint(bb[4 * WS3]);
                    #pragma unroll
                    for (int mi = 0; mi < 2; mi++)
                        mma_tf32(c[mi][ni], a[mi][0], a[mi][1], a[mi][2], a[mi][3], b0, b1v);
                }
            }
            __syncthreads();
        }

        // epilogue: silu + segment-sum (red.global.add.v2.f32 on C-frag pairs)
        #pragma unroll
        for (int mi = 0; mi < 2; mi++) {
            #pragma unroll
            for (int ni = 0; ni < 4; ni++) {
                int col = wn * 32 + ni * 8 + lr * 2;
                float bias0 = __ldg(b2 + col), bias1 = __ldg(b2 + col + 1);
                int row0 = wm * 32 + mi * 16 + lq;
                {
                    float v0 = silu_f(c[mi][ni][0] + bias0);
                    float v1 = silu_f(c[mi][ni][1] + bias1);
                    float* ap = g_aggr + (size_t)dst_s[row0] * H + col;
                    asm volatile("red.global.add.v2.f32 [%0], {%1,%2};"
                                 :: "l"(ap), "f"(v0), "f"(v1) : "memory");
                }
                {
                    float v0 = silu_f(c[mi][ni][2] + bias0);
                    float v1 = silu_f(c[mi][ni][3] + bias1);
                    float* ap = g_aggr + (size_t)dst_s[row0 + 8] * H + col;
                    asm volatile("red.global.add.v2.f32 [%0], {%1,%2};"
                                 :: "l"(ap), "f"(v0), "f"(v1) : "memory");
                }
            }
        }
    }
}

// ---------------- LN update: x = LN(x + aggr/cnt); also re-zero aggr ----------------
__global__ void ln_update_kernel(const float* __restrict__ lng,
                                 const float* __restrict__ lnb) {
    int n = blockIdx.x, tid = threadIdx.x;   // 128 threads
    __shared__ float sred[4];
    float c = g_cnt[n]; c = (c < 1.0f) ? 1.0f : c;
    size_t off = (size_t)n * H + tid;
    float v = g_x[off] + g_aggr[off] / c;
    g_aggr[off] = 0.0f;                      // ready for next layer
    float s = warp_sum(v);
    if ((tid & 31) == 0) sred[tid >> 5] = s;
    __syncthreads();
    float mean = (sred[0] + sred[1] + sred[2] + sred[3]) * (1.0f / H);
    __syncthreads();
    float d = v - mean;
    s = warp_sum(d * d);
    if ((tid & 31) == 0) sred[tid >> 5] = s;
    __syncthreads();
    float var = (sred[0] + sred[1] + sred[2] + sred[3]) * (1.0f / H);
    g_x[off] = d * rsqrtf(var + EPS) * lng[tid] + lnb[tid];
}

// ---------------- graph pooling ----------------
__global__ void pool_kernel(const int* __restrict__ batch_mapping) {
    int n = blockIdx.x, tid = threadIdx.x;   // 128 threads
    int g = batch_mapping[n];
    atomicAdd(&g_crystal[g * H + tid], g_x[(size_t)n * H + tid]);
    if (tid == 0) atomicAdd(&g_gcnt[g], 1.0f);
}

// ---------------- output head ----------------
__global__ void head_kernel(const float* __restrict__ W1, const float* __restrict__ b1,
                            const float* __restrict__ W2, const float* __restrict__ b2,
                            const float* __restrict__ W3, const float* __restrict__ b3,
                            float* __restrict__ out) {
    __shared__ float cs[H], h1[H], h2[64];
    int g = blockIdx.x, tid = threadIdx.x;   // 128 threads
    float gc = g_gcnt[g]; gc = (gc < 1.0f) ? 1.0f : gc;
    cs[tid] = g_crystal[g * H + tid] / gc;
    __syncthreads();
    float acc = b1[tid];
    #pragma unroll 8
    for (int k = 0; k < H; k++) acc = fmaf(cs[k], W1[k * H + tid], acc);
    h1[tid] = silu_f(acc);
    __syncthreads();
    if (tid < 64) {
        acc = b2[tid];
        #pragma unroll 8
        for (int k = 0; k < H; k++) acc = fmaf(h1[k], W2[k * 64 + tid], acc);
        h2[tid] = silu_f(acc);
    }
    __syncthreads();
    if (tid < 3) {
        acc = b3[tid];
        #pragma unroll
        for (int k = 0; k < 64; k++) acc = fmaf(h2[k], W3[k * 3 + tid], acc);
        out[g * 3 + tid] = acc;
    }
}

// ---------------- launch ----------------
extern "C" void kernel_launch(void* const* d_in, const int* in_sizes, int n_in,
                              void* d_out, int out_size) {
    const float* atom_fea  = (const float*)d_in[0];
    const float* nbr_fea   = (const float*)d_in[1];
    const int*   nbr_idx   = (const int*)d_in[2];
    const int*   batch_map = (const int*)d_in[3];
    const float* emb_w     = (const float*)d_in[4];
    const float* emb_b     = (const float*)d_in[5];
    const float* emb_ln_g  = (const float*)d_in[6];
    const float* emb_ln_b  = (const float*)d_in[7];
    const float* edge_w    = (const float*)d_in[8];
    const float* edge_b    = (const float*)d_in[9];
    const float* conv_w1   = (const float*)d_in[10];
    const float* conv_b1   = (const float*)d_in[11];
    const float* conv_w2   = (const float*)d_in[12];
    const float* conv_b2   = (const float*)d_in[13];
    const float* ln_g      = (const float*)d_in[14];
    const float* ln_b      = (const float*)d_in[15];
    const float* out_w1    = (const float*)d_in[16];
    const float* out_b1    = (const float*)d_in[17];
    const float* out_w2    = (const float*)d_in[18];
    const float* out_b2    = (const float*)d_in[19];
    const float* out_w3    = (const float*)d_in[20];
    const float* out_b3    = (const float*)d_in[21];
    float* out = (float*)d_out;

    cudaFuncSetAttribute(conv_kernel,
                         cudaFuncAttributeMaxDynamicSharedMemorySize, CONV_SMEM);
    cudaFuncSetAttribute(xw_kernel,
                         cudaFuncAttributeMaxDynamicSharedMemorySize, XW_SMEM);

    // zero accumulators (covers aggr/crystal/gcnt/cnt)
    init_zero_kernel<<<(N_NODES * H) / 256, 256>>>();
    count_kernel<<<(N_EDGES + 255) / 256, 256>>>(nbr_idx);
    node_embed_kernel<<<N_NODES, H>>>(atom_fea, emb_w, emb_b, emb_ln_g, emb_ln_b);
    edge_embed_kernel<<<N_EDGES / EEDGES, H>>>(nbr_fea, edge_w, edge_b);

    for (int l = 0; l < NLAYERS; l++) {
        const float* W1 = conv_w1 + (size_t)l * 256 * 256;
        xw_kernel<<<(N_NODES + 63) / 64, 256, XW_SMEM>>>(W1);
        conv_kernel<<<N_EDGES / 128, 512, CONV_SMEM>>>(
            nbr_idx,
            W1, conv_b1 + l * 256,
            conv_w2 + (size_t)l * 256 * 128, conv_b2 + l * 128);
        ln_update_kernel<<<N_NODES, H>>>(ln_g + l * H, ln_b + l * H);
    }

    pool_kernel<<<N_NODES, H>>>(batch_map);
    head_kernel<<<N_GRAPHS, H>>>(out_w1, out_b1, out_w2, out_b2, out_w3, out_b3, out);
}

// round 13
// speedup vs baseline: 6.3448x; 1.2817x over previous
#include <cuda_runtime.h>
#include <cuda_bf16.h>
#include <cstddef>
#include <cstdint>

#define N_NODES  50000
#define N_EDGES  800000
#define N_GRAPHS 1024
#define H        128
#define NLAYERS  5
#define EPS      1e-5f

// ---------------- device scratch (static globals; no allocation) ----------------
__device__ float g_x[N_NODES * H];                     // node features fp32
__device__ __nv_bfloat16 g_e[(size_t)N_EDGES * H];     // edge features bf16 (205 MB)
__device__ float g_aggr[N_NODES * H];                  // per-layer aggregation fp32
__device__ float g_xw[(size_t)N_NODES * 2 * H];        // P = x @ W1_top fp32 (51.2 MB)
__device__ __nv_bfloat16 g_w1t[NLAYERS * 256 * 128];   // W1_bot^T bf16 [l][n=256][k=128]
__device__ __nv_bfloat16 g_w2t[NLAYERS * 128 * 256];   // W2^T    bf16 [l][n=128][k=256]
__device__ float g_cnt[N_NODES];
__device__ float g_crystal[N_GRAPHS * H];
__device__ float g_gcnt[N_GRAPHS];

__device__ __forceinline__ float silu_f(float v) {
    return v / (1.0f + __expf(-v));
}

__device__ __forceinline__ float warp_sum(float s) {
    #pragma unroll
    for (int o = 16; o > 0; o >>= 1) s += __shfl_xor_sync(0xffffffffu, s, o);
    return s;
}

// pack two f32 -> bf16x2 (lo = first arg, hi = second arg)
__device__ __forceinline__ uint32_t pack_bf16x2(float lo, float hi) {
    uint32_t r;
    asm("cvt.rn.bf16x2.f32 %0, %1, %2;" : "=r"(r) : "f"(hi), "f"(lo));
    return r;
}

__device__ __forceinline__ void mma_bf16(float c[4],
                                         uint32_t a0, uint32_t a1, uint32_t a2, uint32_t a3,
                                         uint32_t b0, uint32_t b1) {
    asm volatile(
        "mma.sync.aligned.m16n8k16.row.col.f32.bf16.bf16.f32 "
        "{%0,%1,%2,%3}, {%4,%5,%6,%7}, {%8,%9}, {%0,%1,%2,%3};\n"
        : "+f"(c[0]), "+f"(c[1]), "+f"(c[2]), "+f"(c[3])
        : "r"(a0), "r"(a1), "r"(a2), "r"(a3), "r"(b0), "r"(b1));
}

// ---------------- init: zero scratch accumulators ----------------
__global__ void init_zero_kernel() {
    int idx = blockIdx.x * blockDim.x + threadIdx.x;           // grid covers 6.4M exactly
    g_aggr[idx] = 0.0f;
    if (idx < N_GRAPHS * H) g_crystal[idx] = 0.0f;
    if (idx < N_GRAPHS)     g_gcnt[idx] = 0.0f;
    if (idx < N_NODES)      g_cnt[idx] = 0.0f;
}

// ---------------- in-degree count ----------------
__global__ void count_kernel(const int* __restrict__ nbr_idx) {
    int i = blockIdx.x * blockDim.x + threadIdx.x;
    if (i < N_EDGES) atomicAdd(&g_cnt[nbr_idx[2 * i + 1]], 1.0f);
}

// ---------------- weight prep: transpose + bf16 convert (once) ----------------
__global__ void prep_weights_kernel(const float* __restrict__ w1,
                                    const float* __restrict__ w2) {
    int idx = blockIdx.x * blockDim.x + threadIdx.x;   // 0 .. NLAYERS*256*128-1
    if (idx >= NLAYERS * 256 * 128) return;
    int l = idx / (256 * 128);
    int r = idx % (256 * 128);
    {   // g_w1t[l][n][k] = W1[l][128+k][n], n<256, k<128
        int n = r / 128, k = r % 128;
        g_w1t[idx] = __float2bfloat16(w1[(size_t)l * 65536 + (size_t)(128 + k) * 256 + n]);
    }
    {   // g_w2t[l][n][k] = W2[l][k][n], n<128, k<256
        int n = r / 256, k = r % 256;
        g_w2t[idx] = __float2bfloat16(w2[(size_t)l * 32768 + (size_t)k * 128 + n]);
    }
}

// ---------------- node embedding: x = silu(LN(atom @ W + b)) ----------------
__global__ void node_embed_kernel(const float* __restrict__ atom,
                                  const float* __restrict__ W,
                                  const float* __restrict__ bias,
                                  const float* __restrict__ lng,
                                  const float* __restrict__ lnb) {
    int n = blockIdx.x, tid = threadIdx.x;   // 128 threads
    __shared__ float sred[4];
    float4 a = ((const float4*)atom)[n];
    float v = bias[tid] + a.x * W[tid] + a.y * W[H + tid]
                        + a.z * W[2 * H + tid] + a.w * W[3 * H + tid];
    float s = warp_sum(v);
    if ((tid & 31) == 0) sred[tid >> 5] = s;
    __syncthreads();
    float mean = (sred[0] + sred[1] + sred[2] + sred[3]) * (1.0f / H);
    __syncthreads();
    float d = v - mean;
    s = warp_sum(d * d);
    if ((tid & 31) == 0) sred[tid >> 5] = s;
    __syncthreads();
    float var = (sred[0] + sred[1] + sred[2] + sred[3]) * (1.0f / H);
    float y = d * rsqrtf(var + EPS) * lng[tid] + lnb[tid];
    g_x[n * H + tid] = silu_f(y);
}

// ---------------- edge embedding: e = bf16(silu(nbr @ W + b)), K=41 ----------------
#define EEDGES 32
__global__ void edge_embed_kernel(const float* __restrict__ nbr,
                                  const float* __restrict__ W,
                                  const float* __restrict__ bias) {
    __shared__ float nb[EEDGES * 41];
    int tid = threadIdx.x;                     // 128 threads
    int e0 = blockIdx.x * EEDGES;
    float Wc[41];
    #pragma unroll
    for (int k = 0; k < 41; k++) Wc[k] = W[k * H + tid];
    float b = bias[tid];
    for (int idx = tid; idx < EEDGES * 41; idx += 128)
        nb[idx] = nbr[(size_t)e0 * 41 + idx];
    __syncthreads();
    #pragma unroll 4
    for (int r = 0; r < EEDGES; r++) {
        float acc = b;
        #pragma unroll
        for (int k = 0; k < 41; k++) acc = fmaf(nb[r * 41 + k], Wc[k], acc);
        g_e[(size_t)(e0 + r) * H + tid] = __float2bfloat16(silu_f(acc));
    }
}

// ---------------- per-node precompute: P = x @ W1[0:128, :] fp32 ----------------
#define XW_SMEM (64 * 128 * 4 + 16 * 256 * 4)   // 48 KB

__global__ void __launch_bounds__(256, 2)
xw_kernel(const float* __restrict__ W1) {
    extern __shared__ float sm[];
    float* x_s = sm;               // [64][128]
    float* w_s = sm + 64 * 128;    // [16][256]

    int tid = threadIdx.x;
    int wid = tid >> 5, lane = tid & 31;
    int n0 = blockIdx.x * 64;

    for (int r = wid; r < 64; r += 8) {
        int node = n0 + r;
        int nsafe = (node < N_NODES) ? node : 0;
        ((float4*)(x_s + r * 128))[lane] =
            ((const float4*)(g_x + (size_t)nsafe * H))[lane];
    }
    __syncthreads();

    int tm = tid >> 4;
    int tn = tid & 15;

    float acc[4][16];
    #pragma unroll
    for (int i = 0; i < 4; i++)
        #pragma unroll
        for (int j = 0; j < 16; j++) acc[i][j] = 0.0f;

    for (int k0 = 0; k0 < 128; k0 += 16) {
        const float4* wsrc = (const float4*)(W1 + (size_t)k0 * 256);
        float4* wdst = (float4*)w_s;
        #pragma unroll
        for (int t = 0; t < 4; t++) wdst[tid + t * 256] = wsrc[tid + t * 256];
        __syncthreads();
        #pragma unroll
        for (int kk = 0; kk < 16; kk += 4) {
            float4 a4[4];
            #pragma unroll
            for (int i = 0; i < 4; i++)
                a4[i] = *(const float4*)(x_s + (tm * 4 + i) * 128 + k0 + kk);
            #pragma unroll
            for (int q = 0; q < 4; q++) {
                const float* wrow = w_s + (kk + q) * 256 + tn * 16;
                float4 w0 = ((const float4*)wrow)[0];
                float4 w1v = ((const float4*)wrow)[1];
                float4 w2v = ((const float4*)wrow)[2];
                float4 w3v = ((const float4*)wrow)[3];
                float wb[16] = {w0.x, w0.y, w0.z, w0.w,  w1v.x, w1v.y, w1v.z, w1v.w,
                                w2v.x, w2v.y, w2v.z, w2v.w, w3v.x, w3v.y, w3v.z, w3v.w};
                #pragma unroll
                for (int i = 0; i < 4; i++) {
                    float av = ((const float*)&a4[i])[q];
                    #pragma unroll
                    for (int j = 0; j < 16; j++)
                        acc[i][j] = fmaf(av, wb[j], acc[i][j]);
                }
            }
        }
        __syncthreads();
    }

    #pragma unroll
    for (int i = 0; i < 4; i++) {
        int node = n0 + tm * 4 + i;
        if (node < N_NODES) {
            float* dst = g_xw + (size_t)node * 256 + tn * 16;
            #pragma unroll
            for (int j = 0; j < 16; j++) dst[j] = acc[i][j];
        }
    }
}

// ---------------- fused conv layer, bf16 mma.sync version ----------------
// Block: 512 threads (16 warps), tile of 128 edges, 1 CTA/SM.
//   e_s  [128][136] bf16  : edge features                       34816 B
//   P_s  [128][260] fp32  : gathered P[src] (aliased by h1b)   133120 B
//   h1b  [128][264] bf16  : h1 after stage2 (alias of P_s)      67584 B
//   w_s  2 x [256][24] bf16 : ping-pong weight K-tiles          24576 B
//   dst_s[128]                                                    512 B
#define ESB 136     // e_s stride (bf16)
#define PS  260     // P_s stride (fp32)
#define HBS 264     // h1b stride (bf16); 132 words, 132%32=4 -> conflict-free frags
#define WKS 24      // weight tile stride per n-row (bf16); 12 words -> conflict-free
#define SM_E   0
#define SM_P   (128 * ESB * 2)                 // 34816
#define SM_W   (SM_P + 128 * PS * 4)           // 167936
#define SM_DST (SM_W + 2 * 256 * WKS * 2)      // 192512
#define CONV_SMEM (SM_DST + 128 * 4)           // 193024

__global__ void __launch_bounds__(512, 1)
conv_kernel(const int* __restrict__ nbr_idx, int layer,
            const float* __restrict__ b1, const float* __restrict__ b2) {
    const __nv_bfloat16* __restrict__ w1t = g_w1t + (size_t)layer * 256 * 128;
    const __nv_bfloat16* __restrict__ w2t = g_w2t + (size_t)layer * 128 * 256;

    extern __shared__ char smc[];
    __nv_bfloat16* e_s = (__nv_bfloat16*)(smc + SM_E);
    float*         P_s = (float*)(smc + SM_P);
    __nv_bfloat16* h1b = (__nv_bfloat16*)(smc + SM_P);   // alias, used after P consumed
    __nv_bfloat16* w_s = (__nv_bfloat16*)(smc + SM_W);
    int*         dst_s = (int*)(smc + SM_DST);

    int tid  = threadIdx.x;
    int wid  = tid >> 5, lane = tid & 31;
    int lq   = lane >> 2;          // 0..7
    int lr   = lane & 3;           // 0..3
    int e0   = blockIdx.x * 128;

    // ---- gather: P_s <- P[src] (fp32), e_s <- bf16 e tile ----
    for (int r = wid; r < 128; r += 16) {
        int edge = e0 + r;
        int src = nbr_idx[2 * edge];
        if (lane == 0) dst_s[r] = nbr_idx[2 * edge + 1];
        const float4* psrc = (const float4*)(g_xw + (size_t)src * 256);
        *(float4*)(P_s + r * PS + lane * 4)       = psrc[lane];
        *(float4*)(P_s + r * PS + 128 + lane * 4) = psrc[lane + 32];
        *(uint2*)(e_s + r * ESB + lane * 4) =
            ((const uint2*)(g_e + (size_t)edge * H))[lane];
    }

    // ---- stage W1_bot tile 0 into buf 0 ----
    {
        int n = tid >> 1, half = tid & 1;
        *(uint4*)(w_s + n * WKS + half * 8) =
            *(const uint4*)(w1t + (size_t)n * 128 + half * 8);
    }
    __syncthreads();

    int wm = wid >> 2;     // 4 m-tiles of 32 rows
    int wn = wid & 3;      // 4 n-tiles

    // ---- stage 2: h1 = silu(P + e @ W1_bot + b1), 128x256, K=128 ----
    float c[2][8][4];
    #pragma unroll
    for (int mi = 0; mi < 2; mi++)
        #pragma unroll
        for (int ni = 0; ni < 8; ni++)
            #pragma unroll
            for (int q = 0; q < 4; q++) c[mi][ni][q] = 0.0f;

    {
        int sn = tid >> 1, shalf = tid & 1;
        #pragma unroll 1
        for (int kt = 0; kt < 8; kt++) {
            uint4 nxt;
            if (kt + 1 < 8)
                nxt = *(const uint4*)(w1t + (size_t)sn * 128 + (kt + 1) * 16 + shalf * 8);
            const __nv_bfloat16* wb = w_s + (kt & 1) * 256 * WKS;

            uint32_t a[2][4];
            #pragma unroll
            for (int mi = 0; mi < 2; mi++) {
                const __nv_bfloat16* ab = e_s + (wm * 32 + mi * 16 + lq) * ESB + kt * 16 + 2 * lr;
                a[mi][0] = *(const uint32_t*)(ab);
                a[mi][1] = *(const uint32_t*)(ab + 8 * ESB);
                a[mi][2] = *(const uint32_t*)(ab + 8);
                a[mi][3] = *(const uint32_t*)(ab + 8 * ESB + 8);
            }
            #pragma unroll
            for (int ni = 0; ni < 8; ni++) {
                const __nv_bfloat16* bbp = wb + (wn * 64 + ni * 8 + lq) * WKS + 2 * lr;
                uint32_t b0  = *(const uint32_t*)(bbp);
                uint32_t b1v = *(const uint32_t*)(bbp + 8);
                mma_bf16(c[0][ni], a[0][0], a[0][1], a[0][2], a[0][3], b0, b1v);
                mma_bf16(c[1][ni], a[1][0], a[1][1], a[1][2], a[1][3], b0, b1v);
            }
            if (kt + 1 < 8)
                *(uint4*)(w_s + ((kt + 1) & 1) * 256 * WKS + sn * WKS + shalf * 8) = nxt;
            __syncthreads();
        }
    }

    // ---- stage W2 tile 0 into buf 0 (overlaps epilogue phase 1) ----
    if (tid < 256) {
        int n = tid >> 1, half = tid & 1;
        *(uint4*)(w_s + n * WKS + half * 8) =
            *(const uint4*)(w2t + (size_t)n * 256 + half * 8);
    }

    // ---- stage2 epilogue phase 1: fold P + bias + silu into c (registers) ----
    #pragma unroll
    for (int mi = 0; mi < 2; mi++) {
        #pragma unroll
        for (int ni = 0; ni < 8; ni++) {
            int row0 = wm * 32 + mi * 16 + lq;
            int col  = wn * 64 + ni * 8 + 2 * lr;
            float bias0 = __ldg(b1 + col), bias1 = __ldg(b1 + col + 1);
            float2 p0 = *(const float2*)(P_s + row0 * PS + col);
            float2 p1 = *(const float2*)(P_s + (row0 + 8) * PS + col);
            c[mi][ni][0] = silu_f(c[mi][ni][0] + bias0 + p0.x);
            c[mi][ni][1] = silu_f(c[mi][ni][1] + bias1 + p0.y);
            c[mi][ni][2] = silu_f(c[mi][ni][2] + bias0 + p1.x);
            c[mi][ni][3] = silu_f(c[mi][ni][3] + bias1 + p1.y);
        }
    }
    __syncthreads();

    // ---- phase 2: write h1 as bf16x2 into h1b (aliases P_s; all P consumed) ----
    {
        uint32_t* h1w = (uint32_t*)h1b;
        #pragma unroll
        for (int mi = 0; mi < 2; mi++) {
            #pragma unroll
            for (int ni = 0; ni < 8; ni++) {
                int row0 = wm * 32 + mi * 16 + lq;
                int colw = wn * 32 + ni * 4 + lr;   // word index of bf16 pair
                h1w[row0 * (HBS / 2) + colw]       = pack_bf16x2(c[mi][ni][0], c[mi][ni][1]);
                h1w[(row0 + 8) * (HBS / 2) + colw] = pack_bf16x2(c[mi][ni][2], c[mi][ni][3]);
            }
        }
    }
    __syncthreads();

    // ---- stage 3: h2 = silu(h1 @ W2 + b2), 128x128, K=256; scatter-add ----
    float c2[2][4][4];
    #pragma unroll
    for (int mi = 0; mi < 2; mi++)
        #pragma unroll
        for (int ni = 0; ni < 4; ni++)
            #pragma unroll
            for (int q = 0; q < 4; q++) c2[mi][ni][q] = 0.0f;

    {
        int sn = tid >> 1, shalf = tid & 1;
        #pragma unroll 1
        for (int kt = 0; kt < 16; kt++) {
            uint4 nxt;
            if (kt + 1 < 16 && tid < 256)
                nxt = *(const uint4*)(w2t + (size_t)sn * 256 + (kt + 1) * 16 + shalf * 8);
            const __nv_bfloat16* wb = w_s + (kt & 1) * 256 * WKS;

            uint32_t a[2][4];
            #pragma unroll
            for (int mi = 0; mi < 2; mi++) {
                const __nv_bfloat16* ab = h1b + (wm * 32 + mi * 16 + lq) * HBS + kt * 16 + 2 * lr;
                a[mi][0] = *(const uint32_t*)(ab);
                a[mi][1] = *(const uint32_t*)(ab + 8 * HBS);
                a[mi][2] = *(const uint32_t*)(ab + 8);
                a[mi][3] = *(const uint32_t*)(ab + 8 * HBS + 8);
            }
            #pragma unroll
            for (int ni = 0; ni < 4; ni++) {
                const __nv_bfloat16* bbp = wb + (wn * 32 + ni * 8 + lq) * WKS + 2 * lr;
                uint32_t b0  = *(const uint32_t*)(bbp);
                uint32_t b1v = *(const uint32_t*)(bbp + 8);
                mma_bf16(c2[0][ni], a[0][0], a[0][1], a[0][2], a[0][3], b0, b1v);
                mma_bf16(c2[1][ni], a[1][0], a[1][1], a[1][2], a[1][3], b0, b1v);
            }
            if (kt + 1 < 16 && tid < 256)
                *(uint4*)(w_s + ((kt + 1) & 1) * 256 * WKS + sn * WKS + shalf * 8) = nxt;
            __syncthreads();
        }
    }

    // ---- epilogue: silu + segment-sum (red.global.add.v2.f32) ----
    #pragma unroll
    for (int mi = 0; mi < 2; mi++) {
        #pragma unroll
        for (int ni = 0; ni < 4; ni++) {
            int col = wn * 32 + ni * 8 + 2 * lr;
            float bias0 = __ldg(b2 + col), bias1 = __ldg(b2 + col + 1);
            int row0 = wm * 32 + mi * 16 + lq;
            {
                float v0 = silu_f(c2[mi][ni][0] + bias0);
                float v1 = silu_f(c2[mi][ni][1] + bias1);
                float* ap = g_aggr + (size_t)dst_s[row0] * H + col;
                asm volatile("red.global.add.v2.f32 [%0], {%1,%2};"
                             :: "l"(ap), "f"(v0), "f"(v1) : "memory");
            }
            {
                float v0 = silu_f(c2[mi][ni][2] + bias0);
                float v1 = silu_f(c2[mi][ni][3] + bias1);
                float* ap = g_aggr + (size_t)dst_s[row0 + 8] * H + col;
                asm volatile("red.global.add.v2.f32 [%0], {%1,%2};"
                             :: "l"(ap), "f"(v0), "f"(v1) : "memory");
            }
        }
    }
}

// ---------------- LN update: x = LN(x + aggr/cnt); also re-zero aggr ----------------
__global__ void ln_update_kernel(const float* __restrict__ lng,
                                 const float* __restrict__ lnb) {
    int n = blockIdx.x, tid = threadIdx.x;   // 128 threads
    __shared__ float sred[4];
    float c = g_cnt[n]; c = (c < 1.0f) ? 1.0f : c;
    size_t off = (size_t)n * H + tid;
    float v = g_x[off] + g_aggr[off] / c;
    g_aggr[off] = 0.0f;                      // ready for next layer
    float s = warp_sum(v);
    if ((tid & 31) == 0) sred[tid >> 5] = s;
    __syncthreads();
    float mean = (sred[0] + sred[1] + sred[2] + sred[3]) * (1.0f / H);
    __syncthreads();
    float d = v - mean;
    s = warp_sum(d * d);
    if ((tid & 31) == 0) sred[tid >> 5] = s;
    __syncthreads();
    float var = (sred[0] + sred[1] + sred[2] + sred[3]) * (1.0f / H);
    g_x[off] = d * rsqrtf(var + EPS) * lng[tid] + lnb[tid];
}

// ---------------- graph pooling ----------------
__global__ void pool_kernel(const int* __restrict__ batch_mapping) {
    int n = blockIdx.x, tid = threadIdx.x;   // 128 threads
    int g = batch_mapping[n];
    atomicAdd(&g_crystal[g * H + tid], g_x[(size_t)n * H + tid]);
    if (tid == 0) atomicAdd(&g_gcnt[g], 1.0f);
}

// ---------------- output head ----------------
__global__ void head_kernel(const float* __restrict__ W1, const float* __restrict__ b1,
                            const float* __restrict__ W2, const float* __restrict__ b2,
                            const float* __restrict__ W3, const float* __restrict__ b3,
                            float* __restrict__ out) {
    __shared__ float cs[H], h1[H], h2[64];
    int g = blockIdx.x, tid = threadIdx.x;   // 128 threads
    float gc = g_gcnt[g]; gc = (gc < 1.0f) ? 1.0f : gc;
    cs[tid] = g_crystal[g * H + tid] / gc;
    __syncthreads();
    float acc = b1[tid];
    #pragma unroll 8
    for (int k = 0; k < H; k++) acc = fmaf(cs[k], W1[k * H + tid], acc);
    h1[tid] = silu_f(acc);
    __syncthreads();
    if (tid < 64) {
        acc = b2[tid];
        #pragma unroll 8
        for (int k = 0; k < H; k++) acc = fmaf(h1[k], W2[k * 64 + tid], acc);
        h2[tid] = silu_f(acc);
    }
    __syncthreads();
    if (tid < 3) {
        acc = b3[tid];
        #pragma unroll
        for (int k = 0; k < 64; k++) acc = fmaf(h2[k], W3[k * 3 + tid], acc);
        out[g * 3 + tid] = acc;
    }
}

// ---------------- launch ----------------
extern "C" void kernel_launch(void* const* d_in, const int* in_sizes, int n_in,
                              void* d_out, int out_size) {
    const float* atom_fea  = (const float*)d_in[0];
    const float* nbr_fea   = (const float*)d_in[1];
    const int*   nbr_idx   = (const int*)d_in[2];
    const int*   batch_map = (const int*)d_in[3];
    const float* emb_w     = (const float*)d_in[4];
    const float* emb_b     = (const float*)d_in[5];
    const float* emb_ln_g  = (const float*)d_in[6];
    const float* emb_ln_b  = (const float*)d_in[7];
    const float* edge_w    = (const float*)d_in[8];
    const float* edge_b    = (const float*)d_in[9];
    const float* conv_w1   = (const float*)d_in[10];
    const float* conv_b1   = (const float*)d_in[11];
    const float* conv_w2   = (const float*)d_in[12];
    const float* conv_b2   = (const float*)d_in[13];
    const float* ln_g      = (const float*)d_in[14];
    const float* ln_b      = (const float*)d_in[15];
    const float* out_w1    = (const float*)d_in[16];
    const float* out_b1    = (const float*)d_in[17];
    const float* out_w2    = (const float*)d_in[18];
    const float* out_b2    = (const float*)d_in[19];
    const float* out_w3    = (const float*)d_in[20];
    const float* out_b3    = (const float*)d_in[21];
    float* out = (float*)d_out;

    cudaFuncSetAttribute(conv_kernel,
                         cudaFuncAttributeMaxDynamicSharedMemorySize, CONV_SMEM);
    cudaFuncSetAttribute(xw_kernel,
                         cudaFuncAttributeMaxDynamicSharedMemorySize, XW_SMEM);

    // zero accumulators (covers aggr/crystal/gcnt/cnt)
    init_zero_kernel<<<(N_NODES * H) / 256, 256>>>();
    count_kernel<<<(N_EDGES + 255) / 256, 256>>>(nbr_idx);
    prep_weights_kernel<<<(NLAYERS * 256 * 128 + 255) / 256, 256>>>(conv_w1, conv_w2);
    node_embed_kernel<<<N_NODES, H>>>(atom_fea, emb_w, emb_b, emb_ln_g, emb_ln_b);
    edge_embed_kernel<<<N_EDGES / EEDGES, H>>>(nbr_fea, edge_w, edge_b);

    for (int l = 0; l < NLAYERS; l++) {
        const float* W1 = conv_w1 + (size_t)l * 256 * 256;
        xw_kernel<<<(N_NODES + 63) / 64, 256, XW_SMEM>>>(W1);
        conv_kernel<<<N_EDGES / 128, 512, CONV_SMEM>>>(
            nbr_idx, l, conv_b1 + l * 256, conv_b2 + l * 128);
        ln_update_kernel<<<N_NODES, H>>>(ln_g + l * H, ln_b + l * H);
    }

    pool_kernel<<<N_NODES, H>>>(batch_map);
    head_kernel<<<N_GRAPHS, H>>>(out_w1, out_b1, out_w2, out_b2, out_w3, out_b3, out);
}

// round 14
// speedup vs baseline: 7.7458x; 1.2208x over previous
#include <cuda_runtime.h>
#include <cuda_bf16.h>
#include <cstddef>
#include <cstdint>

#define N_NODES  50000
#define N_EDGES  800000
#define N_GRAPHS 1024
#define H        128
#define NLAYERS  5
#define EPS      1e-5f

// ---------------- device scratch (static globals; no allocation) ----------------
__device__ float g_x[N_NODES * H];                       // node features fp32
__device__ __nv_bfloat16 g_e[(size_t)N_EDGES * H];       // edge features bf16 (205 MB)
__device__ float g_aggr[N_NODES * H];                    // per-layer aggregation fp32
__device__ __nv_bfloat16 g_xwb[(size_t)N_NODES * 2 * H]; // P = x @ W1_top bf16 (25.6 MB)
__device__ __nv_bfloat16 g_w1t[NLAYERS * 256 * 128];     // W1_bot^T bf16 [l][n=256][k=128]
__device__ __nv_bfloat16 g_w1tt[NLAYERS * 256 * 128];    // W1_top^T bf16 [l][n=256][k=128]
__device__ __nv_bfloat16 g_w2t[NLAYERS * 128 * 256];     // W2^T    bf16 [l][n=128][k=256]
__device__ float g_cnt[N_NODES];
__device__ float g_crystal[N_GRAPHS * H];
__device__ float g_gcnt[N_GRAPHS];

__device__ __forceinline__ float silu_f(float v) {
    return v / (1.0f + __expf(-v));
}

__device__ __forceinline__ float warp_sum(float s) {
    #pragma unroll
    for (int o = 16; o > 0; o >>= 1) s += __shfl_xor_sync(0xffffffffu, s, o);
    return s;
}

// pack two f32 -> bf16x2 (lo = first arg, hi = second arg)
__device__ __forceinline__ uint32_t pack_bf16x2(float lo, float hi) {
    uint32_t r;
    asm("cvt.rn.bf16x2.f32 %0, %1, %2;" : "=r"(r) : "f"(hi), "f"(lo));
    return r;
}

__device__ __forceinline__ void mma_bf16(float c[4],
                                         uint32_t a0, uint32_t a1, uint32_t a2, uint32_t a3,
                                         uint32_t b0, uint32_t b1) {
    asm volatile(
        "mma.sync.aligned.m16n8k16.row.col.f32.bf16.bf16.f32 "
        "{%0,%1,%2,%3}, {%4,%5,%6,%7}, {%8,%9}, {%0,%1,%2,%3};\n"
        : "+f"(c[0]), "+f"(c[1]), "+f"(c[2]), "+f"(c[3])
        : "r"(a0), "r"(a1), "r"(a2), "r"(a3), "r"(b0), "r"(b1));
}

// ---------------- init: zero scratch accumulators ----------------
__global__ void init_zero_kernel() {
    int idx = blockIdx.x * blockDim.x + threadIdx.x;           // grid covers 6.4M exactly
    g_aggr[idx] = 0.0f;
    if (idx < N_GRAPHS * H) g_crystal[idx] = 0.0f;
    if (idx < N_GRAPHS)     g_gcnt[idx] = 0.0f;
    if (idx < N_NODES)      g_cnt[idx] = 0.0f;
}

// ---------------- in-degree count ----------------
__global__ void count_kernel(const int* __restrict__ nbr_idx) {
    int i = blockIdx.x * blockDim.x + threadIdx.x;
    if (i < N_EDGES) atomicAdd(&g_cnt[nbr_idx[2 * i + 1]], 1.0f);
}

// ---------------- weight prep: transpose + bf16 convert (once) ----------------
__global__ void prep_weights_kernel(const float* __restrict__ w1,
                                    const float* __restrict__ w2) {
    int idx = blockIdx.x * blockDim.x + threadIdx.x;   // 0 .. NLAYERS*256*128-1
    if (idx >= NLAYERS * 256 * 128) return;
    int l = idx / (256 * 128);
    int r = idx % (256 * 128);
    {   // g_w1t[l][n][k]  = W1[l][128+k][n];  g_w1tt[l][n][k] = W1[l][k][n]
        int n = r / 128, k = r % 128;
        g_w1t[idx]  = __float2bfloat16(w1[(size_t)l * 65536 + (size_t)(128 + k) * 256 + n]);
        g_w1tt[idx] = __float2bfloat16(w1[(size_t)l * 65536 + (size_t)k * 256 + n]);
    }
    {   // g_w2t[l][n][k] = W2[l][k][n], n<128, k<256
        int n = r / 256, k = r % 256;
        g_w2t[idx] = __float2bfloat16(w2[(size_t)l * 32768 + (size_t)k * 128 + n]);
    }
}

// ---------------- node embedding: x = silu(LN(atom @ W + b)) ----------------
__global__ void node_embed_kernel(const float* __restrict__ atom,
                                  const float* __restrict__ W,
                                  const float* __restrict__ bias,
                                  const float* __restrict__ lng,
                                  const float* __restrict__ lnb) {
    int n = blockIdx.x, tid = threadIdx.x;   // 128 threads
    __shared__ float sred[4];
    float4 a = ((const float4*)atom)[n];
    float v = bias[tid] + a.x * W[tid] + a.y * W[H + tid]
                        + a.z * W[2 * H + tid] + a.w * W[3 * H + tid];
    float s = warp_sum(v);
    if ((tid & 31) == 0) sred[tid >> 5] = s;
    __syncthreads();
    float mean = (sred[0] + sred[1] + sred[2] + sred[3]) * (1.0f / H);
    __syncthreads();
    float d = v - mean;
    s = warp_sum(d * d);
    if ((tid & 31) == 0) sred[tid >> 5] = s;
    __syncthreads();
    float var = (sred[0] + sred[1] + sred[2] + sred[3]) * (1.0f / H);
    float y = d * rsqrtf(var + EPS) * lng[tid] + lnb[tid];
    g_x[n * H + tid] = silu_f(y);
}

// ---------------- edge embedding: e = bf16(silu(nbr @ W + b)), K=41 ----------------
#define EEDGES 32
__global__ void edge_embed_kernel(const float* __restrict__ nbr,
                                  const float* __restrict__ W,
                                  const float* __restrict__ bias) {
    __shared__ float nb[EEDGES * 41];
    int tid = threadIdx.x;                     // 128 threads
    int e0 = blockIdx.x * EEDGES;
    float Wc[41];
    #pragma unroll
    for (int k = 0; k < 41; k++) Wc[k] = W[k * H + tid];
    float b = bias[tid];
    for (int idx = tid; idx < EEDGES * 41; idx += 128)
        nb[idx] = nbr[(size_t)e0 * 41 + idx];
    __syncthreads();
    #pragma unroll 4
    for (int r = 0; r < EEDGES; r++) {
        float acc = b;
        #pragma unroll
        for (int k = 0; k < 41; k++) acc = fmaf(nb[r * 41 + k], Wc[k], acc);
        g_e[(size_t)(e0 + r) * H + tid] = __float2bfloat16(silu_f(acc));
    }
}

// ---------------- per-node precompute: P = bf16(x @ W1_top), bf16 mma ----------------
// Block: 512 threads (16 warps), tile of 128 nodes, 2 CTAs/SM.
//   x_s [128][136] bf16 : node features          34816 B
//   w_s 2 x [256][24] bf16 : ping-pong W tiles   24576 B
#define XSB 136
#define WKS 24
#define XW_SMEM (128 * XSB * 2 + 2 * 256 * WKS * 2)   // 59392 B

__global__ void __launch_bounds__(512, 2)
xw_kernel(int layer) {
    const __nv_bfloat16* __restrict__ w1tt = g_w1tt + (size_t)layer * 256 * 128;
    extern __shared__ char smx[];
    __nv_bfloat16* x_s = (__nv_bfloat16*)smx;
    __nv_bfloat16* w_s = (__nv_bfloat16*)(smx + 128 * XSB * 2);

    int tid  = threadIdx.x;
    int wid  = tid >> 5, lane = tid & 31;
    int lq   = lane >> 2;
    int lr   = lane & 3;
    int n0   = blockIdx.x * 128;

    // gather x rows (fp32 -> bf16), sequential
    for (int r = wid; r < 128; r += 16) {
        int node = n0 + r;
        int nsafe = (node < N_NODES) ? node : 0;
        float4 v = ((const float4*)(g_x + (size_t)nsafe * H))[lane];
        uint2 p;
        p.x = pack_bf16x2(v.x, v.y);
        p.y = pack_bf16x2(v.z, v.w);
        *(uint2*)(x_s + r * XSB + lane * 4) = p;
    }
    // stage W tile 0
    {
        int n = tid >> 1, half = tid & 1;
        *(uint4*)(w_s + n * WKS + half * 8) =
            *(const uint4*)(w1tt + (size_t)n * 128 + half * 8);
    }
    __syncthreads();

    int wm = wid >> 2;
    int wn = wid & 3;

    float c[2][8][4];
    #pragma unroll
    for (int mi = 0; mi < 2; mi++)
        #pragma unroll
        for (int ni = 0; ni < 8; ni++)
            #pragma unroll
            for (int q = 0; q < 4; q++) c[mi][ni][q] = 0.0f;

    {
        int sn = tid >> 1, shalf = tid & 1;
        #pragma unroll 1
        for (int kt = 0; kt < 8; kt++) {
            uint4 nxt;
            if (kt + 1 < 8)
                nxt = *(const uint4*)(w1tt + (size_t)sn * 128 + (kt + 1) * 16 + shalf * 8);
            const __nv_bfloat16* wb = w_s + (kt & 1) * 256 * WKS;

            uint32_t a[2][4];
            #pragma unroll
            for (int mi = 0; mi < 2; mi++) {
                const __nv_bfloat16* ab = x_s + (wm * 32 + mi * 16 + lq) * XSB + kt * 16 + 2 * lr;
                a[mi][0] = *(const uint32_t*)(ab);
                a[mi][1] = *(const uint32_t*)(ab + 8 * XSB);
                a[mi][2] = *(const uint32_t*)(ab + 8);
                a[mi][3] = *(const uint32_t*)(ab + 8 * XSB + 8);
            }
            #pragma unroll
            for (int ni = 0; ni < 8; ni++) {
                const __nv_bfloat16* bbp = wb + (wn * 64 + ni * 8 + lq) * WKS + 2 * lr;
                uint32_t b0  = *(const uint32_t*)(bbp);
                uint32_t b1v = *(const uint32_t*)(bbp + 8);
                mma_bf16(c[0][ni], a[0][0], a[0][1], a[0][2], a[0][3], b0, b1v);
                mma_bf16(c[1][ni], a[1][0], a[1][1], a[1][2], a[1][3], b0, b1v);
            }
            if (kt + 1 < 8)
                *(uint4*)(w_s + ((kt + 1) & 1) * 256 * WKS + sn * WKS + shalf * 8) = nxt;
            __syncthreads();
        }
    }

    // store P bf16 pairs
    uint32_t* dst = (uint32_t*)g_xwb;
    #pragma unroll
    for (int mi = 0; mi < 2; mi++) {
        #pragma unroll
        for (int ni = 0; ni < 8; ni++) {
            int row0 = wm * 32 + mi * 16 + lq;
            int colw = wn * 32 + ni * 4 + lr;    // pair index within 128
            int nodeA = n0 + row0, nodeB = nodeA + 8;
            if (nodeA < N_NODES)
                dst[(size_t)nodeA * 128 + colw] = pack_bf16x2(c[mi][ni][0], c[mi][ni][1]);
            if (nodeB < N_NODES)
                dst[(size_t)nodeB * 128 + colw] = pack_bf16x2(c[mi][ni][2], c[mi][ni][3]);
        }
    }
}

// ---------------- fused conv layer, bf16 mma.sync ----------------
// Block: 512 threads (16 warps), tile of 128 edges, 1 CTA/SM.
//   e_s  [128][136] bf16 : edge features                         34816 B
//   P_s  [128][264] bf16 : gathered P[src]; becomes h1 in place  67584 B
//   w_s  2 x [256][24] bf16 : ping-pong weight K-tiles           24576 B
//   dst_s[128]                                                     512 B
#define ESB 136
#define HBS 264
#define SM_E   0
#define SM_P   (128 * ESB * 2)                 // 34816
#define SM_W   (SM_P + 128 * HBS * 2)          // 102400
#define SM_DST (SM_W + 2 * 256 * WKS * 2)      // 126976
#define CONV_SMEM (SM_DST + 128 * 4)           // 127488

__global__ void __launch_bounds__(512, 1)
conv_kernel(const int* __restrict__ nbr_idx, int layer,
            const float* __restrict__ b1, const float* __restrict__ b2) {
    const __nv_bfloat16* __restrict__ w1t = g_w1t + (size_t)layer * 256 * 128;
    const __nv_bfloat16* __restrict__ w2t = g_w2t + (size_t)layer * 128 * 256;

    extern __shared__ char smc[];
    __nv_bfloat16* e_s = (__nv_bfloat16*)(smc + SM_E);
    __nv_bfloat16* P_s = (__nv_bfloat16*)(smc + SM_P);   // P, then h1 (same addresses)
    __nv_bfloat16* w_s = (__nv_bfloat16*)(smc + SM_W);
    int*         dst_s = (int*)(smc + SM_DST);

    int tid  = threadIdx.x;
    int wid  = tid >> 5, lane = tid & 31;
    int lq   = lane >> 2;
    int lr   = lane & 3;
    int e0   = blockIdx.x * 128;

    // ---- gather: P_s <- bf16 P[src], e_s <- bf16 e tile ----
    for (int r = wid; r < 128; r += 16) {
        int edge = e0 + r;
        int src = nbr_idx[2 * edge];
        if (lane == 0) dst_s[r] = nbr_idx[2 * edge + 1];
        *(uint4*)(P_s + r * HBS + lane * 8) =
            ((const uint4*)(g_xwb + (size_t)src * 256))[lane];
        *(uint2*)(e_s + r * ESB + lane * 4) =
            ((const uint2*)(g_e + (size_t)edge * H))[lane];
    }

    // ---- stage W1_bot tile 0 into buf 0 ----
    {
        int n = tid >> 1, half = tid & 1;
        *(uint4*)(w_s + n * WKS + half * 8) =
            *(const uint4*)(w1t + (size_t)n * 128 + half * 8);
    }
    __syncthreads();

    int wm = wid >> 2;     // 4 m-tiles of 32 rows
    int wn = wid & 3;      // 4 n-tiles

    // ---- stage 2: h1 = silu(P + e @ W1_bot + b1), 128x256, K=128 ----
    float c[2][8][4];
    #pragma unroll
    for (int mi = 0; mi < 2; mi++)
        #pragma unroll
        for (int ni = 0; ni < 8; ni++)
            #pragma unroll
            for (int q = 0; q < 4; q++) c[mi][ni][q] = 0.0f;

    {
        int sn = tid >> 1, shalf = tid & 1;
        #pragma unroll 1
        for (int kt = 0; kt < 8; kt++) {
            uint4 nxt;
            if (kt + 1 < 8)
                nxt = *(const uint4*)(w1t + (size_t)sn * 128 + (kt + 1) * 16 + shalf * 8);
            const __nv_bfloat16* wb = w_s + (kt & 1) * 256 * WKS;

            uint32_t a[2][4];
            #pragma unroll
            for (int mi = 0; mi < 2; mi++) {
                const __nv_bfloat16* ab = e_s + (wm * 32 + mi * 16 + lq) * ESB + kt * 16 + 2 * lr;
                a[mi][0] = *(const uint32_t*)(ab);
                a[mi][1] = *(const uint32_t*)(ab + 8 * ESB);
                a[mi][2] = *(const uint32_t*)(ab + 8);
                a[mi][3] = *(const uint32_t*)(ab + 8 * ESB + 8);
            }
            #pragma unroll
            for (int ni = 0; ni < 8; ni++) {
                const __nv_bfloat16* bbp = wb + (wn * 64 + ni * 8 + lq) * WKS + 2 * lr;
                uint32_t b0  = *(const uint32_t*)(bbp);
                uint32_t b1v = *(const uint32_t*)(bbp + 8);
                mma_bf16(c[0][ni], a[0][0], a[0][1], a[0][2], a[0][3], b0, b1v);
                mma_bf16(c[1][ni], a[1][0], a[1][1], a[1][2], a[1][3], b0, b1v);
            }
            if (kt + 1 < 8)
                *(uint4*)(w_s + ((kt + 1) & 1) * 256 * WKS + sn * WKS + shalf * 8) = nxt;
            __syncthreads();
        }
    }

    // ---- stage W2 tile 0 into buf 0 (last stage2 kt used buf 1) ----
    if (tid < 256) {
        int n = tid >> 1, half = tid & 1;
        *(uint4*)(w_s + n * WKS + half * 8) =
            *(const uint4*)(w2t + (size_t)n * 256 + half * 8);
    }

    // ---- stage2 epilogue: fold P + bias + silu, write h1 bf16 in place ----
    // Each (row,col) slot is read and then written by the SAME thread -> no barrier.
    {
        uint32_t* hw = (uint32_t*)P_s;
        #pragma unroll
        for (int mi = 0; mi < 2; mi++) {
            #pragma unroll
            for (int ni = 0; ni < 8; ni++) {
                int row0 = wm * 32 + mi * 16 + lq;
                int colw = wn * 32 + ni * 4 + lr;             // bf16-pair index
                int col  = 2 * colw;
                float bias0 = __ldg(b1 + col), bias1 = __ldg(b1 + col + 1);
                uint32_t* s0 = hw + row0 * (HBS / 2) + colw;
                uint32_t* s1 = hw + (row0 + 8) * (HBS / 2) + colw;
                float2 p0 = __bfloat1622float2(*(__nv_bfloat162*)s0);
                float2 p1 = __bfloat1622float2(*(__nv_bfloat162*)s1);
                *s0 = pack_bf16x2(silu_f(c[mi][ni][0] + bias0 + p0.x),
                                  silu_f(c[mi][ni][1] + bias1 + p0.y));
                *s1 = pack_bf16x2(silu_f(c[mi][ni][2] + bias0 + p1.x),
                                  silu_f(c[mi][ni][3] + bias1 + p1.y));
            }
        }
    }
    __syncthreads();

    // ---- stage 3: h2 = silu(h1 @ W2 + b2), 128x128, K=256; scatter-add ----
    float c2[2][4][4];
    #pragma unroll
    for (int mi = 0; mi < 2; mi++)
        #pragma unroll
        for (int ni = 0; ni < 4; ni++)
            #pragma unroll
            for (int q = 0; q < 4; q++) c2[mi][ni][q] = 0.0f;

    {
        int sn = tid >> 1, shalf = tid & 1;
        #pragma unroll 1
        for (int kt = 0; kt < 16; kt++) {
            uint4 nxt;
            if (kt + 1 < 16 && tid < 256)
                nxt = *(const uint4*)(w2t + (size_t)sn * 256 + (kt + 1) * 16 + shalf * 8);
            const __nv_bfloat16* wb = w_s + (kt & 1) * 256 * WKS;

            uint32_t a[2][4];
            #pragma unroll
            for (int mi = 0; mi < 2; mi++) {
                const __nv_bfloat16* ab = P_s + (wm * 32 + mi * 16 + lq) * HBS + kt * 16 + 2 * lr;
                a[mi][0] = *(const uint32_t*)(ab);
                a[mi][1] = *(const uint32_t*)(ab + 8 * HBS);
                a[mi][2] = *(const uint32_t*)(ab + 8);
                a[mi][3] = *(const uint32_t*)(ab + 8 * HBS + 8);
            }
            #pragma unroll
            for (int ni = 0; ni < 4; ni++) {
                const __nv_bfloat16* bbp = wb + (wn * 32 + ni * 8 + lq) * WKS + 2 * lr;
                uint32_t b0  = *(const uint32_t*)(bbp);
                uint32_t b1v = *(const uint32_t*)(bbp + 8);
                mma_bf16(c2[0][ni], a[0][0], a[0][1], a[0][2], a[0][3], b0, b1v);
                mma_bf16(c2[1][ni], a[1][0], a[1][1], a[1][2], a[1][3], b0, b1v);
            }
            if (kt + 1 < 16 && tid < 256)
                *(uint4*)(w_s + ((kt + 1) & 1) * 256 * WKS + sn * WKS + shalf * 8) = nxt;
            __syncthreads();
        }
    }

    // ---- epilogue: silu + segment-sum (red.global.add.v2.f32) ----
    #pragma unroll
    for (int mi = 0; mi < 2; mi++) {
        #pragma unroll
        for (int ni = 0; ni < 4; ni++) {
            int col = wn * 32 + ni * 8 + 2 * lr;
            float bias0 = __ldg(b2 + col), bias1 = __ldg(b2 + col + 1);
            int row0 = wm * 32 + mi * 16 + lq;
            {
                float v0 = silu_f(c2[mi][ni][0] + bias0);
                float v1 = silu_f(c2[mi][ni][1] + bias1);
                float* ap = g_aggr + (size_t)dst_s[row0] * H + col;
                asm volatile("red.global.add.v2.f32 [%0], {%1,%2};"
                             :: "l"(ap), "f"(v0), "f"(v1) : "memory");
            }
            {
                float v0 = silu_f(c2[mi][ni][2] + bias0);
                float v1 = silu_f(c2[mi][ni][3] + bias1);
                float* ap = g_aggr + (size_t)dst_s[row0 + 8] * H + col;
                asm volatile("red.global.add.v2.f32 [%0], {%1,%2};"
                             :: "l"(ap), "f"(v0), "f"(v1) : "memory");
            }
        }
    }
}

// ---------------- LN update: x = LN(x + aggr/cnt); also re-zero aggr ----------------
__global__ void ln_update_kernel(const float* __restrict__ lng,
                                 const float* __restrict__ lnb) {
    int n = blockIdx.x, tid = threadIdx.x;   // 128 threads
    __shared__ float sred[4];
    float c = g_cnt[n]; c = (c < 1.0f) ? 1.0f : c;
    size_t off = (size_t)n * H + tid;
    float v = g_x[off] + g_aggr[off] / c;
    g_aggr[off] = 0.0f;                      // ready for next layer
    float s = warp_sum(v);
    if ((tid & 31) == 0) sred[tid >> 5] = s;
    __syncthreads();
    float mean = (sred[0] + sred[1] + sred[2] + sred[3]) * (1.0f / H);
    __syncthreads();
    float d = v - mean;
    s = warp_sum(d * d);
    if ((tid & 31) == 0) sred[tid >> 5] = s;
    __syncthreads();
    float var = (sred[0] + sred[1] + sred[2] + sred[3]) * (1.0f / H);
    g_x[off] = d * rsqrtf(var + EPS) * lng[tid] + lnb[tid];
}

// ---------------- graph pooling ----------------
__global__ void pool_kernel(const int* __restrict__ batch_mapping) {
    int n = blockIdx.x, tid = threadIdx.x;   // 128 threads
    int g = batch_mapping[n];
    atomicAdd(&g_crystal[g * H + tid], g_x[(size_t)n * H + tid]);
    if (tid == 0) atomicAdd(&g_gcnt[g], 1.0f);
}

// ---------------- output head ----------------
__global__ void head_kernel(const float* __restrict__ W1, const float* __restrict__ b1,
                            const float* __restrict__ W2, const float* __restrict__ b2,
                            const float* __restrict__ W3, const float* __restrict__ b3,
                            float* __restrict__ out) {
    __shared__ float cs[H], h1[H], h2[64];
    int g = blockIdx.x, tid = threadIdx.x;   // 128 threads
    float gc = g_gcnt[g]; gc = (gc < 1.0f) ? 1.0f : gc;
    cs[tid] = g_crystal[g * H + tid] / gc;
    __syncthreads();
    float acc = b1[tid];
    #pragma unroll 8
    for (int k = 0; k < H; k++) acc = fmaf(cs[k], W1[k * H + tid], acc);
    h1[tid] = silu_f(acc);
    __syncthreads();
    if (tid < 64) {
        acc = b2[tid];
        #pragma unroll 8
        for (int k = 0; k < H; k++) acc = fmaf(h1[k], W2[k * 64 + tid], acc);
        h2[tid] = silu_f(acc);
    }
    __syncthreads();
    if (tid < 3) {
        acc = b3[tid];
        #pragma unroll
        for (int k = 0; k < 64; k++) acc = fmaf(h2[k], W3[k * 3 + tid], acc);
        out[g * 3 + tid] = acc;
    }
}

// ---------------- launch ----------------
extern "C" void kernel_launch(void* const* d_in, const int* in_sizes, int n_in,
                              void* d_out, int out_size) {
    const float* atom_fea  = (const float*)d_in[0];
    const float* nbr_fea   = (const float*)d_in[1];
    const int*   nbr_idx   = (const int*)d_in[2];
    const int*   batch_map = (const int*)d_in[3];
    const float* emb_w     = (const float*)d_in[4];
    const float* emb_b     = (const float*)d_in[5];
    const float* emb_ln_g  = (const float*)d_in[6];
    const float* emb_ln_b  = (const float*)d_in[7];
    const float* edge_w    = (const float*)d_in[8];
    const float* edge_b    = (const float*)d_in[9];
    const float* conv_w1   = (const float*)d_in[10];
    const float* conv_b1   = (const float*)d_in[11];
    const float* conv_w2   = (const float*)d_in[12];
    const float* conv_b2   = (const float*)d_in[13];
    const float* ln_g      = (const float*)d_in[14];
    const float* ln_b      = (const float*)d_in[15];
    const float* out_w1    = (const float*)d_in[16];
    const float* out_b1    = (const float*)d_in[17];
    const float* out_w2    = (const float*)d_in[18];
    const float* out_b2    = (const float*)d_in[19];
    const float* out_w3    = (const float*)d_in[20];
    const float* out_b3    = (const float*)d_in[21];
    float* out = (float*)d_out;

    cudaFuncSetAttribute(conv_kernel,
                         cudaFuncAttributeMaxDynamicSharedMemorySize, CONV_SMEM);
    cudaFuncSetAttribute(xw_kernel,
                         cudaFuncAttributeMaxDynamicSharedMemorySize, XW_SMEM);

    // zero accumulators (covers aggr/crystal/gcnt/cnt)
    init_zero_kernel<<<(N_NODES * H) / 256, 256>>>();
    count_kernel<<<(N_EDGES + 255) / 256, 256>>>(nbr_idx);
    prep_weights_kernel<<<(NLAYERS * 256 * 128 + 255) / 256, 256>>>(conv_w1, conv_w2);
    node_embed_kernel<<<N_NODES, H>>>(atom_fea, emb_w, emb_b, emb_ln_g, emb_ln_b);
    edge_embed_kernel<<<N_EDGES / EEDGES, H>>>(nbr_fea, edge_w, edge_b);

    for (int l = 0; l < NLAYERS; l++) {
        xw_kernel<<<(N_NODES + 127) / 128, 512, XW_SMEM>>>(l);
        conv_kernel<<<N_EDGES / 128, 512, CONV_SMEM>>>(
            nbr_idx, l, conv_b1 + l * 256, conv_b2 + l * 128);
        ln_update_kernel<<<N_NODES, H>>>(ln_g + l * H, ln_b + l * H);
    }

    pool_kernel<<<N_NODES, H>>>(batch_map);
    head_kernel<<<N_GRAPHS, H>>>(out_w1, out_b1, out_w2, out_b2, out_w3, out_b3, out);
}